// round 1
// baseline (speedup 1.0000x reference)
#include <cuda_runtime.h>
#include <cuda_bf16.h>
#include <math.h>

// ---------------- problem constants ----------------
#define TOKENS   32768          // 2 * 128 * 128
#define DIM      384
#define NHEADS   8
#define HD       48
#define HID      1536
#define NWIN     128            // 2 * 8 * 8 windows of 256 tokens
#define WTOK     256            // tokens per window
#define SCALE    0.14433756729740643f   // 48^-0.5
#define LN_EPS   1e-5f

// ---------------- scratch (static device arrays; no allocations) ----------------
__device__ float g_h  [(size_t)TOKENS * DIM];    // residual stream (window layout)
__device__ float g_ln [(size_t)TOKENS * DIM];    // layernorm output
__device__ float g_qkv[(size_t)TOKENS * 3 * DIM];// qkv projection
__device__ float g_att[(size_t)TOKENS * DIM];    // attention output (pre-proj)
__device__ float g_hid[(size_t)TOKENS * HID];    // mlp hidden

// ---------------- window partition / unpartition ----------------
// h[win][n][c] = x[b][wy*16+yi][wx*16+xi][c],  win=b*64+wy*8+wx, n=yi*16+xi
__global__ void partition_kernel(const float* __restrict__ x, float* __restrict__ h) {
    int idx = blockIdx.x * 256 + threadIdx.x;       // over TOKENS*96 float4s
    int c4  = idx % 96;
    int tok = idx / 96;
    int n   = tok & 255;
    int win = tok >> 8;
    int wx = win & 7, wy = (win >> 3) & 7, b = win >> 6;
    int yi = n >> 4, xi = n & 15;
    size_t src = ((((size_t)b * 128 + wy * 16 + yi) * 128) + wx * 16 + xi) * 96 + c4;
    ((float4*)h)[idx] = ((const float4*)x)[src];
}

__global__ void unpartition_kernel(const float* __restrict__ h, float* __restrict__ out) {
    int idx = blockIdx.x * 256 + threadIdx.x;
    int c4  = idx % 96;
    int tok = idx / 96;
    int n   = tok & 255;
    int win = tok >> 8;
    int wx = win & 7, wy = (win >> 3) & 7, b = win >> 6;
    int yi = n >> 4, xi = n & 15;
    size_t dst = ((((size_t)b * 128 + wy * 16 + yi) * 128) + wx * 16 + xi) * 96 + c4;
    ((float4*)out)[dst] = ((const float4*)h)[idx];
}

// ---------------- layernorm: one warp per token (C=384 = 12 per lane) ----------------
__global__ void ln_kernel(const float* __restrict__ in, const float* __restrict__ g,
                          const float* __restrict__ b, float* __restrict__ out) {
    int token = blockIdx.x * 8 + (threadIdx.x >> 5);
    int lane  = threadIdx.x & 31;
    const float* row = in + (size_t)token * DIM;
    float v[12];
    float s = 0.f;
    #pragma unroll
    for (int i = 0; i < 12; i++) { v[i] = row[lane + i * 32]; s += v[i]; }
    #pragma unroll
    for (int o = 16; o; o >>= 1) s += __shfl_xor_sync(0xffffffffu, s, o);
    float mu = s * (1.f / DIM);
    float vsum = 0.f;
    #pragma unroll
    for (int i = 0; i < 12; i++) { float d = v[i] - mu; vsum += d * d; }
    #pragma unroll
    for (int o = 16; o; o >>= 1) vsum += __shfl_xor_sync(0xffffffffu, vsum, o);
    float rstd = rsqrtf(vsum * (1.f / DIM) + LN_EPS);
    float* orow = out + (size_t)token * DIM;
    #pragma unroll
    for (int i = 0; i < 12; i++) {
        int c = lane + i * 32;
        orow[c] = (v[i] - mu) * rstd * g[c] + b[c];
    }
}

// ---------------- SGEMM 128x128x8, 256 threads, 8x8 per-thread tile ----------------
// MODE 0: C = A@B          (no bias)
// MODE 1: C = gelu(A@B + bias)
// MODE 2: C += A@B + bias  (residual accumulate)
__device__ __forceinline__ float gelu_f(float x) {
    return 0.5f * x * (1.0f + erff(x * 0.70710678118654752f));
}

template<int MODE>
__global__ void __launch_bounds__(256)
sgemm_kernel(const float* __restrict__ A, const float* __restrict__ B,
             const float* __restrict__ bias, float* __restrict__ C,
             int M, int N, int K) {
    __shared__ float As[8][128];
    __shared__ float Bs[8][128];
    int tid = threadIdx.x;
    int ty = tid >> 4, tx = tid & 15;
    int bm = blockIdx.y * 128, bn = blockIdx.x * 128;

    int arow = tid >> 1;            // 0..127
    int acol = (tid & 1) * 4;       // 0 or 4
    int brow = tid >> 5;            // 0..7
    int bcol = (tid & 31) * 4;      // 0..124

    const float* Aptr = A + (size_t)(bm + arow) * K + acol;
    const float* Bptr = B + (size_t)brow * N + bn + bcol;

    float acc[8][8];
    #pragma unroll
    for (int i = 0; i < 8; i++)
        #pragma unroll
        for (int j = 0; j < 8; j++) acc[i][j] = 0.f;

    for (int k0 = 0; k0 < K; k0 += 8) {
        float4 av = *(const float4*)Aptr; Aptr += 8;
        float4 bv = *(const float4*)Bptr; Bptr += (size_t)8 * N;
        As[acol + 0][arow] = av.x;
        As[acol + 1][arow] = av.y;
        As[acol + 2][arow] = av.z;
        As[acol + 3][arow] = av.w;
        *(float4*)&Bs[brow][bcol] = bv;
        __syncthreads();
        #pragma unroll
        for (int k = 0; k < 8; k++) {
            float4 a0 = *(const float4*)&As[k][ty * 8];
            float4 a1 = *(const float4*)&As[k][ty * 8 + 4];
            float4 b0 = *(const float4*)&Bs[k][tx * 8];
            float4 b1 = *(const float4*)&Bs[k][tx * 8 + 4];
            float ar[8] = {a0.x, a0.y, a0.z, a0.w, a1.x, a1.y, a1.z, a1.w};
            float br[8] = {b0.x, b0.y, b0.z, b0.w, b1.x, b1.y, b1.z, b1.w};
            #pragma unroll
            for (int i = 0; i < 8; i++)
                #pragma unroll
                for (int j = 0; j < 8; j++)
                    acc[i][j] += ar[i] * br[j];
        }
        __syncthreads();
    }

    // epilogue
    float bval[8];
    if (MODE != 0) {
        const float* bp = bias + bn + tx * 8;
        #pragma unroll
        for (int j = 0; j < 8; j++) bval[j] = bp[j];
    }
    #pragma unroll
    for (int i = 0; i < 8; i++) {
        size_t row = (size_t)(bm + ty * 8 + i);
        float* cp = C + row * N + bn + tx * 8;
        if (MODE == 0) {
            float4 o0 = make_float4(acc[i][0], acc[i][1], acc[i][2], acc[i][3]);
            float4 o1 = make_float4(acc[i][4], acc[i][5], acc[i][6], acc[i][7]);
            *(float4*)cp = o0;
            *(float4*)(cp + 4) = o1;
        } else if (MODE == 1) {
            float v[8];
            #pragma unroll
            for (int j = 0; j < 8; j++) v[j] = gelu_f(acc[i][j] + bval[j]);
            *(float4*)cp = make_float4(v[0], v[1], v[2], v[3]);
            *(float4*)(cp + 4) = make_float4(v[4], v[5], v[6], v[7]);
        } else {
            float4 c0 = *(const float4*)cp;
            float4 c1 = *(const float4*)(cp + 4);
            c0.x += acc[i][0] + bval[0]; c0.y += acc[i][1] + bval[1];
            c0.z += acc[i][2] + bval[2]; c0.w += acc[i][3] + bval[3];
            c1.x += acc[i][4] + bval[4]; c1.y += acc[i][5] + bval[5];
            c1.z += acc[i][6] + bval[6]; c1.w += acc[i][7] + bval[7];
            *(float4*)cp = c0;
            *(float4*)(cp + 4) = c1;
        }
    }
}

// ---------------- windowed attention: one CTA per (head, window) ----------------
// Each thread owns one query row (256 threads = 256 queries), online softmax,
// K/V for this (window, head) staged in dynamic smem (2 * 256 * 48 * 4 = 96KB).
__global__ void __launch_bounds__(256)
attn_kernel(const float* __restrict__ qkv, const float* __restrict__ rpb,
            float* __restrict__ out) {
    extern __shared__ float smem[];
    float* ks = smem;                 // [256][48]
    float* vs = smem + WTOK * HD;     // [256][48]

    int head = blockIdx.x;
    int win  = blockIdx.y;
    int n    = threadIdx.x;
    size_t base = (size_t)win * WTOK;

    const float* kbase = qkv + base * (3 * DIM) + DIM     + head * HD;
    const float* vbase = qkv + base * (3 * DIM) + 2 * DIM + head * HD;
    for (int idx = n; idx < WTOK * 12; idx += 256) {
        int m  = idx / 12;
        int d4 = (idx % 12) * 4;
        *(float4*)&ks[m * HD + d4] = *(const float4*)(kbase + (size_t)m * (3 * DIM) + d4);
        *(float4*)&vs[m * HD + d4] = *(const float4*)(vbase + (size_t)m * (3 * DIM) + d4);
    }
    __syncthreads();

    float q[HD];
    const float* qrow = qkv + (base + n) * (3 * DIM) + head * HD;
    #pragma unroll
    for (int d4 = 0; d4 < HD; d4 += 4) {
        float4 t = *(const float4*)(qrow + d4);
        q[d4 + 0] = t.x * SCALE; q[d4 + 1] = t.y * SCALE;
        q[d4 + 2] = t.z * SCALE; q[d4 + 3] = t.w * SCALE;
    }

    int yi = n >> 4, xi = n & 15;
    float mmax = -1e30f, l = 0.f;
    float o[HD];
    #pragma unroll
    for (int d = 0; d < HD; d++) o[d] = 0.f;

    for (int m0 = 0; m0 < WTOK; m0 += 8) {
        float s[8];
        #pragma unroll
        for (int j = 0; j < 8; j++) {
            const float* kr = &ks[(m0 + j) * HD];
            float a = 0.f;
            #pragma unroll
            for (int d = 0; d < HD; d++) a += q[d] * kr[d];
            int mm = m0 + j;
            int yj = mm >> 4, xj = mm & 15;
            int ridx = (yi - yj + 15) * 31 + (xi - xj + 15);
            s[j] = a + __ldg(rpb + ridx * NHEADS + head);
        }
        float cm = s[0];
        #pragma unroll
        for (int j = 1; j < 8; j++) cm = fmaxf(cm, s[j]);
        float nm = fmaxf(mmax, cm);
        float f = __expf(mmax - nm);
        float p[8], ps = 0.f;
        #pragma unroll
        for (int j = 0; j < 8; j++) { p[j] = __expf(s[j] - nm); ps += p[j]; }
        l = l * f + ps;
        #pragma unroll
        for (int d = 0; d < HD; d++) {
            float a = o[d] * f;
            #pragma unroll
            for (int j = 0; j < 8; j++) a += p[j] * vs[(m0 + j) * HD + d];
            o[d] = a;
        }
        mmax = nm;
    }

    float inv = 1.f / l;
    float* orow = out + (base + n) * DIM + head * HD;
    #pragma unroll
    for (int d4 = 0; d4 < HD; d4 += 4) {
        float4 t = make_float4(o[d4] * inv, o[d4 + 1] * inv, o[d4 + 2] * inv, o[d4 + 3] * inv);
        *(float4*)(orow + d4) = t;
    }
}

// ---------------- host launcher ----------------
extern "C" void kernel_launch(void* const* d_in, const int* in_sizes, int n_in,
                              void* d_out, int out_size) {
    const float* x      = (const float*)d_in[0];
    const float* qkv_w  = (const float*)d_in[1];
    const float* proj_w = (const float*)d_in[2];
    const float* proj_b = (const float*)d_in[3];
    const float* rpb    = (const float*)d_in[4];
    const float* ln1_g  = (const float*)d_in[5];
    const float* ln1_b  = (const float*)d_in[6];
    const float* ln2_g  = (const float*)d_in[7];
    const float* ln2_b  = (const float*)d_in[8];
    const float* fc1_w  = (const float*)d_in[9];
    const float* fc1_b  = (const float*)d_in[10];
    const float* fc2_w  = (const float*)d_in[11];
    const float* fc2_b  = (const float*)d_in[12];

    float *h, *ln, *qkv, *att, *hid;
    cudaGetSymbolAddress((void**)&h,   g_h);
    cudaGetSymbolAddress((void**)&ln,  g_ln);
    cudaGetSymbolAddress((void**)&qkv, g_qkv);
    cudaGetSymbolAddress((void**)&att, g_att);
    cudaGetSymbolAddress((void**)&hid, g_hid);

    const int ATTN_SMEM = 2 * WTOK * HD * (int)sizeof(float); // 96 KB
    cudaFuncSetAttribute(attn_kernel, cudaFuncAttributeMaxDynamicSharedMemorySize, ATTN_SMEM);

    // partition x into window-token layout
    partition_kernel<<<TOKENS * 96 / 256, 256>>>(x, h);

    for (int i = 0; i < 2; i++) {
        // LN1
        ln_kernel<<<TOKENS / 8, 256>>>(h, ln1_g + i * DIM, ln1_b + i * DIM, ln);
        // QKV: [32768,384] @ [384,1152]
        sgemm_kernel<0><<<dim3(1152 / 128, TOKENS / 128), 256>>>(
            ln, qkv_w + (size_t)i * DIM * 3 * DIM, nullptr, qkv, TOKENS, 3 * DIM, DIM);
        // windowed attention
        attn_kernel<<<dim3(NHEADS, NWIN), 256, ATTN_SMEM>>>(
            qkv, rpb + (size_t)i * 961 * NHEADS, att);
        // proj + bias + residual: h += att @ proj_w + proj_b
        sgemm_kernel<2><<<dim3(DIM / 128, TOKENS / 128), 256>>>(
            att, proj_w + (size_t)i * DIM * DIM, proj_b + (size_t)i * DIM, h,
            TOKENS, DIM, DIM);
        // LN2
        ln_kernel<<<TOKENS / 8, 256>>>(h, ln2_g + i * DIM, ln2_b + i * DIM, ln);
        // FC1 + bias + gelu
        sgemm_kernel<1><<<dim3(HID / 128, TOKENS / 128), 256>>>(
            ln, fc1_w + (size_t)i * DIM * HID, fc1_b + (size_t)i * HID, hid,
            TOKENS, HID, DIM);
        // FC2 + bias + residual
        sgemm_kernel<2><<<dim3(DIM / 128, TOKENS / 128), 256>>>(
            hid, fc2_w + (size_t)i * HID * DIM, fc2_b + (size_t)i * DIM, h,
            TOKENS, DIM, HID);
    }

    // un-partition into (B,H,W,C)
    unpartition_kernel<<<TOKENS * 96 / 256, 256>>>(h, (float*)d_out);
}

// round 2
// speedup vs baseline: 1.9203x; 1.9203x over previous
#include <cuda_runtime.h>
#include <cuda_bf16.h>
#include <math.h>
#include <stdint.h>

// ---------------- problem constants ----------------
#define TOKENS   32768          // 2 * 128 * 128
#define DIM      384
#define NHEADS   8
#define HD       48
#define HID      1536
#define NWIN     128            // 2 * 8 * 8 windows of 256 tokens
#define WTOK     256            // tokens per window
#define SCALE    0.14433756729740643f   // 48^-0.5
#define LN_EPS   1e-5f

// ---------------- scratch (static device arrays; no allocations) ----------------
__device__ float g_h  [(size_t)TOKENS * DIM];    // residual stream (window layout)
__device__ float g_ln [(size_t)TOKENS * DIM];    // layernorm output
__device__ float g_qkv[(size_t)TOKENS * 3 * DIM];// qkv projection
__device__ float g_att[(size_t)TOKENS * DIM];    // attention output (pre-proj)
__device__ float g_hid[(size_t)TOKENS * HID];    // mlp hidden

// ---------------- window partition / unpartition ----------------
__global__ void partition_kernel(const float* __restrict__ x, float* __restrict__ h) {
    int idx = blockIdx.x * 256 + threadIdx.x;       // over TOKENS*96 float4s
    int c4  = idx % 96;
    int tok = idx / 96;
    int n   = tok & 255;
    int win = tok >> 8;
    int wx = win & 7, wy = (win >> 3) & 7, b = win >> 6;
    int yi = n >> 4, xi = n & 15;
    size_t src = ((((size_t)b * 128 + wy * 16 + yi) * 128) + wx * 16 + xi) * 96 + c4;
    ((float4*)h)[idx] = ((const float4*)x)[src];
}

__global__ void unpartition_kernel(const float* __restrict__ h, float* __restrict__ out) {
    int idx = blockIdx.x * 256 + threadIdx.x;
    int c4  = idx % 96;
    int tok = idx / 96;
    int n   = tok & 255;
    int win = tok >> 8;
    int wx = win & 7, wy = (win >> 3) & 7, b = win >> 6;
    int yi = n >> 4, xi = n & 15;
    size_t dst = ((((size_t)b * 128 + wy * 16 + yi) * 128) + wx * 16 + xi) * 96 + c4;
    ((float4*)out)[dst] = ((const float4*)h)[idx];
}

// ---------------- layernorm: one warp per token ----------------
__global__ void ln_kernel(const float* __restrict__ in, const float* __restrict__ g,
                          const float* __restrict__ b, float* __restrict__ out) {
    int token = blockIdx.x * 8 + (threadIdx.x >> 5);
    int lane  = threadIdx.x & 31;
    const float* row = in + (size_t)token * DIM;
    float v[12];
    float s = 0.f;
    #pragma unroll
    for (int i = 0; i < 12; i++) { v[i] = row[lane + i * 32]; s += v[i]; }
    #pragma unroll
    for (int o = 16; o; o >>= 1) s += __shfl_xor_sync(0xffffffffu, s, o);
    float mu = s * (1.f / DIM);
    float vsum = 0.f;
    #pragma unroll
    for (int i = 0; i < 12; i++) { float d = v[i] - mu; vsum += d * d; }
    #pragma unroll
    for (int o = 16; o; o >>= 1) vsum += __shfl_xor_sync(0xffffffffu, vsum, o);
    float rstd = rsqrtf(vsum * (1.f / DIM) + LN_EPS);
    float* orow = out + (size_t)token * DIM;
    #pragma unroll
    for (int i = 0; i < 12; i++) {
        int c = lane + i * 32;
        orow[c] = (v[i] - mu) * rstd * g[c] + b[c];
    }
}

// ---------------- tf32 tensor-core GEMM 128x128x32 ----------------
// MODE 0: C = A@B
// MODE 1: C = gelu(A@B + bias)
// MODE 2: C += A@B + bias
__device__ __forceinline__ float gelu_f(float x) {
    return 0.5f * x * (1.0f + erff(x * 0.70710678118654752f));
}

__device__ __forceinline__ float f2tf32(float f) {
    uint32_t u;
    asm("cvt.rna.tf32.f32 %0, %1;" : "=r"(u) : "f"(f));
    return __uint_as_float(u);
}

#define AS_STR 36      // 128 rows x 36 (padded from 32)
#define BS_STR 132     // 32 rows x 132 (padded from 128)
#define AS_TILE (128 * AS_STR)
#define BS_TILE (32 * BS_STR)
#define GSMEM ((2 * AS_TILE + 2 * BS_TILE) * (int)sizeof(float))

__device__ __forceinline__ void mma_tf32(float* d, const uint32_t* a, const uint32_t* b) {
    asm volatile(
        "mma.sync.aligned.m16n8k8.row.col.f32.tf32.tf32.f32 "
        "{%0,%1,%2,%3}, {%4,%5,%6,%7}, {%8,%9}, {%0,%1,%2,%3};"
        : "+f"(d[0]), "+f"(d[1]), "+f"(d[2]), "+f"(d[3])
        : "r"(a[0]), "r"(a[1]), "r"(a[2]), "r"(a[3]), "r"(b[0]), "r"(b[1]));
}

template<int MODE>
__global__ void __launch_bounds__(256)
tgemm_kernel(const float* __restrict__ A, const float* __restrict__ B,
             const float* __restrict__ bias, float* __restrict__ C,
             int M, int N, int K) {
    extern __shared__ float smem[];
    float* As = smem;                  // [2][128][AS_STR]
    float* Bs = smem + 2 * AS_TILE;    // [2][32][BS_STR]

    int tid  = threadIdx.x;
    int lane = tid & 31, wid = tid >> 5;
    int gid  = lane >> 2, tig = lane & 3;
    int wm   = wid & 3,  wn  = wid >> 2;     // warp grid 4 x 2
    int bm   = blockIdx.y * 128, bn = blockIdx.x * 128;

    // gmem load assignments (4 float4 each for A and B per K-tile)
    int aRow0 = tid >> 3;         // +32 per i
    int aCol  = (tid & 7) * 4;
    int bRow0 = tid >> 5;         // +8 per i
    int bCol  = (tid & 31) * 4;

    const float* Ag = A + (size_t)(bm + aRow0) * K + aCol;
    const float* Bg = B + (size_t)bRow0 * N + bn + bCol;

    float acc[2][8][4];
    #pragma unroll
    for (int mt = 0; mt < 2; mt++)
        #pragma unroll
        for (int nt = 0; nt < 8; nt++)
            #pragma unroll
            for (int r = 0; r < 4; r++) acc[mt][nt][r] = 0.f;

    int T = K / 32;
    float4 aR[4], bR[4];

    // prefetch tile 0
    #pragma unroll
    for (int i = 0; i < 4; i++) aR[i] = *(const float4*)(Ag + (size_t)i * 32 * K);
    #pragma unroll
    for (int i = 0; i < 4; i++) bR[i] = *(const float4*)(Bg + (size_t)i * 8 * N);
    // store tile 0 to buffer 0 (converted to tf32)
    {
        float* as = As;
        float* bs = Bs;
        #pragma unroll
        for (int i = 0; i < 4; i++) {
            float4 v = make_float4(f2tf32(aR[i].x), f2tf32(aR[i].y), f2tf32(aR[i].z), f2tf32(aR[i].w));
            *(float4*)(as + (size_t)(aRow0 + i * 32) * AS_STR + aCol) = v;
            float4 w = make_float4(f2tf32(bR[i].x), f2tf32(bR[i].y), f2tf32(bR[i].z), f2tf32(bR[i].w));
            *(float4*)(bs + (size_t)(bRow0 + i * 8) * BS_STR + bCol) = w;
        }
    }
    __syncthreads();

    for (int t = 0; t < T; t++) {
        int cur = t & 1;
        // prefetch next tile into registers
        if (t + 1 < T) {
            const float* ap = Ag + (t + 1) * 32;
            const float* bp = Bg + (size_t)(t + 1) * 32 * N;
            #pragma unroll
            for (int i = 0; i < 4; i++) aR[i] = *(const float4*)(ap + (size_t)i * 32 * K);
            #pragma unroll
            for (int i = 0; i < 4; i++) bR[i] = *(const float4*)(bp + (size_t)i * 8 * N);
        }
        // compute on current buffer
        const float* as = As + cur * AS_TILE;
        const float* bs = Bs + cur * BS_TILE;
        #pragma unroll
        for (int kk = 0; kk < 32; kk += 8) {
            uint32_t af[2][4];
            #pragma unroll
            for (int mt = 0; mt < 2; mt++) {
                int r = wm * 32 + mt * 16 + gid;
                af[mt][0] = __float_as_uint(as[(size_t)r * AS_STR + kk + tig]);
                af[mt][1] = __float_as_uint(as[(size_t)(r + 8) * AS_STR + kk + tig]);
                af[mt][2] = __float_as_uint(as[(size_t)r * AS_STR + kk + tig + 4]);
                af[mt][3] = __float_as_uint(as[(size_t)(r + 8) * AS_STR + kk + tig + 4]);
            }
            uint32_t bf[8][2];
            #pragma unroll
            for (int nt = 0; nt < 8; nt++) {
                int c = wn * 64 + nt * 8 + gid;
                bf[nt][0] = __float_as_uint(bs[(size_t)(kk + tig) * BS_STR + c]);
                bf[nt][1] = __float_as_uint(bs[(size_t)(kk + tig + 4) * BS_STR + c]);
            }
            #pragma unroll
            for (int mt = 0; mt < 2; mt++)
                #pragma unroll
                for (int nt = 0; nt < 8; nt++)
                    mma_tf32(acc[mt][nt], af[mt], bf[nt]);
        }
        // store prefetched tile to other buffer
        if (t + 1 < T) {
            float* asn = As + (cur ^ 1) * AS_TILE;
            float* bsn = Bs + (cur ^ 1) * BS_TILE;
            #pragma unroll
            for (int i = 0; i < 4; i++) {
                float4 v = make_float4(f2tf32(aR[i].x), f2tf32(aR[i].y), f2tf32(aR[i].z), f2tf32(aR[i].w));
                *(float4*)(asn + (size_t)(aRow0 + i * 32) * AS_STR + aCol) = v;
                float4 w = make_float4(f2tf32(bR[i].x), f2tf32(bR[i].y), f2tf32(bR[i].z), f2tf32(bR[i].w));
                *(float4*)(bsn + (size_t)(bRow0 + i * 8) * BS_STR + bCol) = w;
            }
            __syncthreads();
        }
    }

    // epilogue
    #pragma unroll
    for (int nt = 0; nt < 8; nt++) {
        int col = bn + wn * 64 + nt * 8 + 2 * tig;
        float2 bv = make_float2(0.f, 0.f);
        if (MODE != 0) { bv.x = bias[col]; bv.y = bias[col + 1]; }
        #pragma unroll
        for (int mt = 0; mt < 2; mt++) {
            int r0 = bm + wm * 32 + mt * 16 + gid;
            #pragma unroll
            for (int h = 0; h < 2; h++) {
                int row = r0 + h * 8;
                float* cp = C + (size_t)row * N + col;
                float v0 = acc[mt][nt][h * 2 + 0];
                float v1 = acc[mt][nt][h * 2 + 1];
                if (MODE == 0) {
                    *(float2*)cp = make_float2(v0, v1);
                } else if (MODE == 1) {
                    *(float2*)cp = make_float2(gelu_f(v0 + bv.x), gelu_f(v1 + bv.y));
                } else {
                    float2 c0 = *(const float2*)cp;
                    c0.x += v0 + bv.x;
                    c0.y += v1 + bv.y;
                    *(float2*)cp = c0;
                }
            }
        }
    }
}

// ---------------- windowed attention: one CTA per (head, window) ----------------
__global__ void __launch_bounds__(256)
attn_kernel(const float* __restrict__ qkv, const float* __restrict__ rpb,
            float* __restrict__ out) {
    extern __shared__ float smem[];
    float* ks = smem;                 // [256][48]
    float* vs = smem + WTOK * HD;     // [256][48]

    int head = blockIdx.x;
    int win  = blockIdx.y;
    int n    = threadIdx.x;
    size_t base = (size_t)win * WTOK;

    const float* kbase = qkv + base * (3 * DIM) + DIM     + head * HD;
    const float* vbase = qkv + base * (3 * DIM) + 2 * DIM + head * HD;
    for (int idx = n; idx < WTOK * 12; idx += 256) {
        int m  = idx / 12;
        int d4 = (idx % 12) * 4;
        *(float4*)&ks[m * HD + d4] = *(const float4*)(kbase + (size_t)m * (3 * DIM) + d4);
        *(float4*)&vs[m * HD + d4] = *(const float4*)(vbase + (size_t)m * (3 * DIM) + d4);
    }
    __syncthreads();

    float q[HD];
    const float* qrow = qkv + (base + n) * (3 * DIM) + head * HD;
    #pragma unroll
    for (int d4 = 0; d4 < HD; d4 += 4) {
        float4 t = *(const float4*)(qrow + d4);
        q[d4 + 0] = t.x * SCALE; q[d4 + 1] = t.y * SCALE;
        q[d4 + 2] = t.z * SCALE; q[d4 + 3] = t.w * SCALE;
    }

    int yi = n >> 4, xi = n & 15;
    float mmax = -1e30f, l = 0.f;
    float o[HD];
    #pragma unroll
    for (int d = 0; d < HD; d++) o[d] = 0.f;

    for (int m0 = 0; m0 < WTOK; m0 += 8) {
        float s[8];
        #pragma unroll
        for (int j = 0; j < 8; j++) {
            const float* kr = &ks[(m0 + j) * HD];
            float a = 0.f;
            #pragma unroll
            for (int d = 0; d < HD; d++) a += q[d] * kr[d];
            int mm = m0 + j;
            int yj = mm >> 4, xj = mm & 15;
            int ridx = (yi - yj + 15) * 31 + (xi - xj + 15);
            s[j] = a + __ldg(rpb + ridx * NHEADS + head);
        }
        float cm = s[0];
        #pragma unroll
        for (int j = 1; j < 8; j++) cm = fmaxf(cm, s[j]);
        float nm = fmaxf(mmax, cm);
        float f = __expf(mmax - nm);
        float p[8], ps = 0.f;
        #pragma unroll
        for (int j = 0; j < 8; j++) { p[j] = __expf(s[j] - nm); ps += p[j]; }
        l = l * f + ps;
        #pragma unroll
        for (int d = 0; d < HD; d++) {
            float a = o[d] * f;
            #pragma unroll
            for (int j = 0; j < 8; j++) a += p[j] * vs[(m0 + j) * HD + d];
            o[d] = a;
        }
        mmax = nm;
    }

    float inv = 1.f / l;
    float* orow = out + (base + n) * DIM + head * HD;
    #pragma unroll
    for (int d4 = 0; d4 < HD; d4 += 4) {
        float4 t = make_float4(o[d4] * inv, o[d4 + 1] * inv, o[d4 + 2] * inv, o[d4 + 3] * inv);
        *(float4*)(orow + d4) = t;
    }
}

// ---------------- host launcher ----------------
extern "C" void kernel_launch(void* const* d_in, const int* in_sizes, int n_in,
                              void* d_out, int out_size) {
    const float* x      = (const float*)d_in[0];
    const float* qkv_w  = (const float*)d_in[1];
    const float* proj_w = (const float*)d_in[2];
    const float* proj_b = (const float*)d_in[3];
    const float* rpb    = (const float*)d_in[4];
    const float* ln1_g  = (const float*)d_in[5];
    const float* ln1_b  = (const float*)d_in[6];
    const float* ln2_g  = (const float*)d_in[7];
    const float* ln2_b  = (const float*)d_in[8];
    const float* fc1_w  = (const float*)d_in[9];
    const float* fc1_b  = (const float*)d_in[10];
    const float* fc2_w  = (const float*)d_in[11];
    const float* fc2_b  = (const float*)d_in[12];

    float *h, *ln, *qkv, *att, *hid;
    cudaGetSymbolAddress((void**)&h,   g_h);
    cudaGetSymbolAddress((void**)&ln,  g_ln);
    cudaGetSymbolAddress((void**)&qkv, g_qkv);
    cudaGetSymbolAddress((void**)&att, g_att);
    cudaGetSymbolAddress((void**)&hid, g_hid);

    const int ATTN_SMEM = 2 * WTOK * HD * (int)sizeof(float); // 96 KB
    static int attr_done = 0;
    if (!attr_done) {
        cudaFuncSetAttribute(attn_kernel, cudaFuncAttributeMaxDynamicSharedMemorySize, ATTN_SMEM);
        cudaFuncSetAttribute(tgemm_kernel<0>, cudaFuncAttributeMaxDynamicSharedMemorySize, GSMEM);
        cudaFuncSetAttribute(tgemm_kernel<1>, cudaFuncAttributeMaxDynamicSharedMemorySize, GSMEM);
        cudaFuncSetAttribute(tgemm_kernel<2>, cudaFuncAttributeMaxDynamicSharedMemorySize, GSMEM);
        attr_done = 1;
    }

    partition_kernel<<<TOKENS * 96 / 256, 256>>>(x, h);

    for (int i = 0; i < 2; i++) {
        ln_kernel<<<TOKENS / 8, 256>>>(h, ln1_g + i * DIM, ln1_b + i * DIM, ln);
        tgemm_kernel<0><<<dim3(1152 / 128, TOKENS / 128), 256, GSMEM>>>(
            ln, qkv_w + (size_t)i * DIM * 3 * DIM, nullptr, qkv, TOKENS, 3 * DIM, DIM);
        attn_kernel<<<dim3(NHEADS, NWIN), 256, ATTN_SMEM>>>(
            qkv, rpb + (size_t)i * 961 * NHEADS, att);
        tgemm_kernel<2><<<dim3(DIM / 128, TOKENS / 128), 256, GSMEM>>>(
            att, proj_w + (size_t)i * DIM * DIM, proj_b + (size_t)i * DIM, h,
            TOKENS, DIM, DIM);
        ln_kernel<<<TOKENS / 8, 256>>>(h, ln2_g + i * DIM, ln2_b + i * DIM, ln);
        tgemm_kernel<1><<<dim3(HID / 128, TOKENS / 128), 256, GSMEM>>>(
            ln, fc1_w + (size_t)i * DIM * HID, fc1_b + (size_t)i * HID, hid,
            TOKENS, HID, DIM);
        tgemm_kernel<2><<<dim3(DIM / 128, TOKENS / 128), 256, GSMEM>>>(
            hid, fc2_w + (size_t)i * HID * DIM, fc2_b + (size_t)i * DIM, h,
            TOKENS, DIM, HID);
    }

    unpartition_kernel<<<TOKENS * 96 / 256, 256>>>(h, (float*)d_out);
}

// round 4
// speedup vs baseline: 2.0306x; 1.0575x over previous
#include <cuda_runtime.h>
#include <cuda_bf16.h>
#include <math.h>
#include <stdint.h>

// ---------------- problem constants ----------------
#define TOKENS   32768
#define DIM      384
#define NHEADS   8
#define HD       48
#define HID      1536
#define NWIN     128
#define WTOK     256
#define SCALE    0.14433756729740643f
#define LN_EPS   1e-5f

// ---------------- scratch ----------------
__device__ float g_h  [(size_t)TOKENS * DIM];
__device__ float g_ln [(size_t)TOKENS * DIM];
__device__ float g_qkv[(size_t)TOKENS * 3 * DIM];
__device__ float g_att[(size_t)TOKENS * DIM];
__device__ float g_hid[(size_t)TOKENS * HID];
// transposed + tf32-rounded + k-permuted weights [N][K]
__device__ float g_qkvwt[(size_t)2 * 3 * DIM * DIM];
__device__ float g_projwt[(size_t)2 * DIM * DIM];
__device__ float g_fc1wt[(size_t)2 * HID * DIM];
__device__ float g_fc2wt[(size_t)2 * DIM * HID];

// ---------------- helpers ----------------
__device__ __forceinline__ uint32_t smem_u32(const void* p) {
    uint32_t a;
    asm("{ .reg .u64 t; cvta.to.shared.u64 t, %1; cvt.u32.u64 %0, t; }" : "=r"(a) : "l"(p));
    return a;
}
__device__ __forceinline__ float f2tf32(float f) {
    uint32_t u;
    asm("cvt.rna.tf32.f32 %0, %1;" : "=r"(u) : "f"(f));
    return __uint_as_float(u);
}
__device__ __forceinline__ void cp16(uint32_t dst, const void* src) {
    asm volatile("cp.async.cg.shared.global [%0], [%1], 16;" :: "r"(dst), "l"(src));
}
__device__ __forceinline__ void cp_commit() {
    asm volatile("cp.async.commit_group;" ::: "memory");
}
template<int N>
__device__ __forceinline__ void cp_wait() {
    asm volatile("cp.async.wait_group %0;" :: "n"(N) : "memory");
}
__device__ __forceinline__ void mma_tf32(float* d, const uint32_t* a, uint32_t b0, uint32_t b1) {
    asm volatile(
        "mma.sync.aligned.m16n8k8.row.col.f32.tf32.tf32.f32 "
        "{%0,%1,%2,%3}, {%4,%5,%6,%7}, {%8,%9}, {%0,%1,%2,%3};"
        : "+f"(d[0]), "+f"(d[1]), "+f"(d[2]), "+f"(d[3])
        : "r"(a[0]), "r"(a[1]), "r"(a[2]), "r"(a[3]), "r"(b0), "r"(b1));
}
__device__ __forceinline__ float gelu_f(float x) {
    return 0.5f * x * (1.0f + erff(x * 0.70710678118654752f));
}

// ---------------- window partition / unpartition ----------------
__global__ void partition_kernel(const float* __restrict__ x, float* __restrict__ h) {
    int idx = blockIdx.x * 256 + threadIdx.x;
    int c4  = idx % 96;
    int tok = idx / 96;
    int n   = tok & 255;
    int win = tok >> 8;
    int wx = win & 7, wy = (win >> 3) & 7, b = win >> 6;
    int yi = n >> 4, xi = n & 15;
    size_t src = ((((size_t)b * 128 + wy * 16 + yi) * 128) + wx * 16 + xi) * 96 + c4;
    ((float4*)h)[idx] = ((const float4*)x)[src];
}

__global__ void unpartition_kernel(const float* __restrict__ h, float* __restrict__ out) {
    int idx = blockIdx.x * 256 + threadIdx.x;
    int c4  = idx % 96;
    int tok = idx / 96;
    int n   = tok & 255;
    int win = tok >> 8;
    int wx = win & 7, wy = (win >> 3) & 7, b = win >> 6;
    int yi = n >> 4, xi = n & 15;
    size_t dst = ((((size_t)b * 128 + wy * 16 + yi) * 128) + wx * 16 + xi) * 96 + c4;
    ((float4*)out)[dst] = ((const float4*)h)[idx];
}

// ---------------- layernorm ----------------
__global__ void ln_kernel(const float* __restrict__ in, const float* __restrict__ g,
                          const float* __restrict__ b, float* __restrict__ out) {
    int token = blockIdx.x * 8 + (threadIdx.x >> 5);
    int lane  = threadIdx.x & 31;
    const float* row = in + (size_t)token * DIM;
    float v[12];
    float s = 0.f;
    #pragma unroll
    for (int i = 0; i < 12; i++) { v[i] = row[lane + i * 32]; s += v[i]; }
    #pragma unroll
    for (int o = 16; o; o >>= 1) s += __shfl_xor_sync(0xffffffffu, s, o);
    float mu = s * (1.f / DIM);
    float vsum = 0.f;
    #pragma unroll
    for (int i = 0; i < 12; i++) { float d = v[i] - mu; vsum += d * d; }
    #pragma unroll
    for (int o = 16; o; o >>= 1) vsum += __shfl_xor_sync(0xffffffffu, vsum, o);
    float rstd = rsqrtf(vsum * (1.f / DIM) + LN_EPS);
    float* orow = out + (size_t)token * DIM;
    #pragma unroll
    for (int i = 0; i < 12; i++) {
        int c = lane + i * 32;
        orow[c] = (v[i] - mu) * rstd * g[c] + b[c];
    }
}

// ---------------- weight transpose: in[K][N] -> out[N][perm(K)] with tf32 round ----------------
// within each 32-block of k: pos = (k%8)*4 + k/8  (enables float4 fragment loads)
__global__ void transpose_kernel(const float* __restrict__ in, float* __restrict__ out,
                                 int K, int N) {
    __shared__ float t[32][33];
    int n0 = blockIdx.x * 32, k0 = blockIdx.y * 32;
    int x = threadIdx.x, y = threadIdx.y;
    #pragma unroll
    for (int i = 0; i < 32; i += 8)
        t[y + i][x] = in[(size_t)(k0 + y + i) * N + n0 + x];
    __syncthreads();
    int pos = (x & 7) * 4 + (x >> 3);
    #pragma unroll
    for (int i = 0; i < 32; i += 8)
        out[(size_t)(n0 + y + i) * K + k0 + pos] = f2tf32(t[x][y + i]);
}

// ---------------- tf32 mma.sync GEMM: 128x128 tile, BK=32, 3-stage cp.async ----------------
// A [M][K] fp32 natural layout; Bt [N][K] pre-transposed, k-permuted, tf32-rounded
#define A_ROW  36                     // floats per A smem row (padded)
#define B_ROW  48                     // floats per B smem row (padded)
#define A_TILE (128 * A_ROW)          // 4608 floats
#define B_TILE (128 * B_ROW)          // 6144 floats
#define STAGE_F (A_TILE + B_TILE)     // 10752 floats
#define NSTAGE 3
#define GEMM_SMEM (NSTAGE * STAGE_F * 4)

template<int MODE>
__global__ void __launch_bounds__(256)
tf_gemm(const float* __restrict__ A, const float* __restrict__ Bt,
        const float* __restrict__ bias, float* __restrict__ C,
        int M, int N, int K) {
    extern __shared__ float smem[];
    uint32_t sbase = smem_u32(smem);

    int tid = threadIdx.x;
    int lane = tid & 31, wid = tid >> 5;
    int gid = lane >> 2, tig = lane & 3;
    int wm = wid & 3, wn = wid >> 2;                 // 4x2 warp grid
    int bm = blockIdx.y * 128, bn = blockIdx.x * 128;

    // copy mapping: 4 x 16B chunks each for A and B per k-tile
    int rowA[4], chA[4];
    #pragma unroll
    for (int i = 0; i < 4; i++) {
        int idx = i * 256 + tid;
        rowA[i] = idx >> 3;
        chA[i]  = idx & 7;
    }

    int T = K / 32;

    auto issue_stage = [&](int t, int slot) {
        uint32_t abase = sbase + (uint32_t)(slot * STAGE_F) * 4;
        uint32_t bbase = abase + (uint32_t)A_TILE * 4;
        #pragma unroll
        for (int i = 0; i < 4; i++) {
            cp16(abase + (uint32_t)(rowA[i] * A_ROW + chA[i] * 4) * 4,
                 A + (size_t)(bm + rowA[i]) * K + t * 32 + chA[i] * 4);
            cp16(bbase + (uint32_t)(rowA[i] * B_ROW + chA[i] * 4) * 4,
                 Bt + (size_t)(bn + rowA[i]) * K + t * 32 + chA[i] * 4);
        }
        cp_commit();
    };

    issue_stage(0, 0);
    issue_stage(1, 1);
    issue_stage(2, 2);

    float acc[2][8][4];
    #pragma unroll
    for (int mt = 0; mt < 2; mt++)
        #pragma unroll
        for (int nt = 0; nt < 8; nt++)
            #pragma unroll
            for (int r = 0; r < 4; r++) acc[mt][nt][r] = 0.f;

    for (int t = 0; t < T; t++) {
        int rem = T - t;
        if (rem > 2)       cp_wait<2>();
        else if (rem == 2) cp_wait<1>();
        else               cp_wait<0>();
        __syncthreads();

        int slot = t % NSTAGE;
        const float* as = smem + slot * STAGE_F;
        const float* bs = as + A_TILE;

        // load all A fragments for this k-tile (32 scalar LDS, conflict-free)
        uint32_t af[2][4][4];
        #pragma unroll
        for (int mt = 0; mt < 2; mt++) {
            int r = wm * 32 + mt * 16 + gid;
            #pragma unroll
            for (int j = 0; j < 4; j++) {
                af[mt][j][0] = __float_as_uint(as[r * A_ROW + j * 8 + tig]);
                af[mt][j][1] = __float_as_uint(as[(r + 8) * A_ROW + j * 8 + tig]);
                af[mt][j][2] = __float_as_uint(as[r * A_ROW + j * 8 + tig + 4]);
                af[mt][j][3] = __float_as_uint(as[(r + 8) * A_ROW + j * 8 + tig + 4]);
            }
        }
        // per nt: 2 x LDS.128 cover all 4 k-steps
        #pragma unroll
        for (int nt = 0; nt < 8; nt++) {
            int n = wn * 64 + nt * 8 + gid;
            float4 b0 = *(const float4*)&bs[n * B_ROW + tig * 4];
            float4 b1 = *(const float4*)&bs[n * B_ROW + tig * 4 + 16];
            uint32_t b0r[4] = {__float_as_uint(b0.x), __float_as_uint(b0.y),
                               __float_as_uint(b0.z), __float_as_uint(b0.w)};
            uint32_t b1r[4] = {__float_as_uint(b1.x), __float_as_uint(b1.y),
                               __float_as_uint(b1.z), __float_as_uint(b1.w)};
            #pragma unroll
            for (int j = 0; j < 4; j++) {
                mma_tf32(acc[0][nt], af[0][j], b0r[j], b1r[j]);
                mma_tf32(acc[1][nt], af[1][j], b0r[j], b1r[j]);
            }
        }
        __syncthreads();
        if (t + 3 < T) issue_stage(t + 3, slot);
    }

    // epilogue: thread owns rows (wm*32+mt*16+gid, +8), cols (wn*64+nt*8+tig*2, +1)
    #pragma unroll
    for (int nt = 0; nt < 8; nt++) {
        int col = bn + wn * 64 + nt * 8 + 2 * tig;
        float2 bv = make_float2(0.f, 0.f);
        if (MODE != 0) { bv.x = bias[col]; bv.y = bias[col + 1]; }
        #pragma unroll
        for (int mt = 0; mt < 2; mt++) {
            int r0 = bm + wm * 32 + mt * 16 + gid;
            #pragma unroll
            for (int h = 0; h < 2; h++) {
                int row = r0 + h * 8;
                float* cp = C + (size_t)row * N + col;
                float v0 = acc[mt][nt][h * 2 + 0];
                float v1 = acc[mt][nt][h * 2 + 1];
                if (MODE == 0) {
                    *(float2*)cp = make_float2(v0, v1);
                } else if (MODE == 1) {
                    *(float2*)cp = make_float2(gelu_f(v0 + bv.x), gelu_f(v1 + bv.y));
                } else {
                    float2 c0 = *(const float2*)cp;
                    c0.x += v0 + bv.x;
                    c0.y += v1 + bv.y;
                    *(float2*)cp = c0;
                }
            }
        }
    }
}

// ---------------- windowed attention ----------------
__global__ void __launch_bounds__(256)
attn_kernel(const float* __restrict__ qkv, const float* __restrict__ rpb,
            float* __restrict__ out) {
    extern __shared__ float smem[];
    float* ks = smem;
    float* vs = smem + WTOK * HD;

    int head = blockIdx.x;
    int win  = blockIdx.y;
    int n    = threadIdx.x;
    size_t base = (size_t)win * WTOK;

    const float* kbase = qkv + base * (3 * DIM) + DIM     + head * HD;
    const float* vbase = qkv + base * (3 * DIM) + 2 * DIM + head * HD;
    for (int idx = n; idx < WTOK * 12; idx += 256) {
        int m  = idx / 12;
        int d4 = (idx % 12) * 4;
        *(float4*)&ks[m * HD + d4] = *(const float4*)(kbase + (size_t)m * (3 * DIM) + d4);
        *(float4*)&vs[m * HD + d4] = *(const float4*)(vbase + (size_t)m * (3 * DIM) + d4);
    }
    __syncthreads();

    float q[HD];
    const float* qrow = qkv + (base + n) * (3 * DIM) + head * HD;
    #pragma unroll
    for (int d4 = 0; d4 < HD; d4 += 4) {
        float4 t = *(const float4*)(qrow + d4);
        q[d4 + 0] = t.x * SCALE; q[d4 + 1] = t.y * SCALE;
        q[d4 + 2] = t.z * SCALE; q[d4 + 3] = t.w * SCALE;
    }

    int yi = n >> 4, xi = n & 15;
    float mmax = -1e30f, l = 0.f;
    float o[HD];
    #pragma unroll
    for (int d = 0; d < HD; d++) o[d] = 0.f;

    for (int m0 = 0; m0 < WTOK; m0 += 8) {
        float s[8];
        #pragma unroll
        for (int j = 0; j < 8; j++) {
            const float* kr = &ks[(m0 + j) * HD];
            float a = 0.f;
            #pragma unroll
            for (int d = 0; d < HD; d++) a += q[d] * kr[d];
            int mm = m0 + j;
            int yj = mm >> 4, xj = mm & 15;
            int ridx = (yi - yj + 15) * 31 + (xi - xj + 15);
            s[j] = a + __ldg(rpb + ridx * NHEADS + head);
        }
        float cm = s[0];
        #pragma unroll
        for (int j = 1; j < 8; j++) cm = fmaxf(cm, s[j]);
        float nm = fmaxf(mmax, cm);
        float f = __expf(mmax - nm);
        float p[8], ps = 0.f;
        #pragma unroll
        for (int j = 0; j < 8; j++) { p[j] = __expf(s[j] - nm); ps += p[j]; }
        l = l * f + ps;
        #pragma unroll
        for (int d = 0; d < HD; d++) {
            float a = o[d] * f;
            #pragma unroll
            for (int j = 0; j < 8; j++) a += p[j] * vs[(m0 + j) * HD + d];
            o[d] = a;
        }
        mmax = nm;
    }

    float inv = 1.f / l;
    float* orow = out + (base + n) * DIM + head * HD;
    #pragma unroll
    for (int d4 = 0; d4 < HD; d4 += 4) {
        float4 t = make_float4(o[d4] * inv, o[d4 + 1] * inv, o[d4 + 2] * inv, o[d4 + 3] * inv);
        *(float4*)(orow + d4) = t;
    }
}

// ---------------- host launcher ----------------
extern "C" void kernel_launch(void* const* d_in, const int* in_sizes, int n_in,
                              void* d_out, int out_size) {
    const float* x      = (const float*)d_in[0];
    const float* qkv_w  = (const float*)d_in[1];
    const float* proj_w = (const float*)d_in[2];
    const float* proj_b = (const float*)d_in[3];
    const float* rpb    = (const float*)d_in[4];
    const float* ln1_g  = (const float*)d_in[5];
    const float* ln1_b  = (const float*)d_in[6];
    const float* ln2_g  = (const float*)d_in[7];
    const float* ln2_b  = (const float*)d_in[8];
    const float* fc1_w  = (const float*)d_in[9];
    const float* fc1_b  = (const float*)d_in[10];
    const float* fc2_w  = (const float*)d_in[11];
    const float* fc2_b  = (const float*)d_in[12];

    float *h, *ln, *qkv, *att, *hid, *qkvwt, *projwt, *fc1wt, *fc2wt;
    cudaGetSymbolAddress((void**)&h,      g_h);
    cudaGetSymbolAddress((void**)&ln,     g_ln);
    cudaGetSymbolAddress((void**)&qkv,    g_qkv);
    cudaGetSymbolAddress((void**)&att,    g_att);
    cudaGetSymbolAddress((void**)&hid,    g_hid);
    cudaGetSymbolAddress((void**)&qkvwt,  g_qkvwt);
    cudaGetSymbolAddress((void**)&projwt, g_projwt);
    cudaGetSymbolAddress((void**)&fc1wt,  g_fc1wt);
    cudaGetSymbolAddress((void**)&fc2wt,  g_fc2wt);

    const int ATTN_SMEM = 2 * WTOK * HD * (int)sizeof(float); // 96 KB
    cudaFuncSetAttribute(attn_kernel, cudaFuncAttributeMaxDynamicSharedMemorySize, ATTN_SMEM);
    cudaFuncSetAttribute(tf_gemm<0>, cudaFuncAttributeMaxDynamicSharedMemorySize, GEMM_SMEM);
    cudaFuncSetAttribute(tf_gemm<1>, cudaFuncAttributeMaxDynamicSharedMemorySize, GEMM_SMEM);
    cudaFuncSetAttribute(tf_gemm<2>, cudaFuncAttributeMaxDynamicSharedMemorySize, GEMM_SMEM);

    dim3 tb(32, 8);
    for (int i = 0; i < 2; i++) {
        transpose_kernel<<<dim3(3 * DIM / 32, DIM / 32), tb>>>(
            qkv_w + (size_t)i * DIM * 3 * DIM, qkvwt + (size_t)i * 3 * DIM * DIM, DIM, 3 * DIM);
        transpose_kernel<<<dim3(DIM / 32, DIM / 32), tb>>>(
            proj_w + (size_t)i * DIM * DIM, projwt + (size_t)i * DIM * DIM, DIM, DIM);
        transpose_kernel<<<dim3(HID / 32, DIM / 32), tb>>>(
            fc1_w + (size_t)i * DIM * HID, fc1wt + (size_t)i * HID * DIM, DIM, HID);
        transpose_kernel<<<dim3(DIM / 32, HID / 32), tb>>>(
            fc2_w + (size_t)i * HID * DIM, fc2wt + (size_t)i * DIM * HID, HID, DIM);
    }

    partition_kernel<<<TOKENS * 96 / 256, 256>>>(x, h);

    for (int i = 0; i < 2; i++) {
        ln_kernel<<<TOKENS / 8, 256>>>(h, ln1_g + i * DIM, ln1_b + i * DIM, ln);
        tf_gemm<0><<<dim3(3 * DIM / 128, TOKENS / 128), 256, GEMM_SMEM>>>(
            ln, qkvwt + (size_t)i * 3 * DIM * DIM, nullptr, qkv, TOKENS, 3 * DIM, DIM);
        attn_kernel<<<dim3(NHEADS, NWIN), 256, ATTN_SMEM>>>(
            qkv, rpb + (size_t)i * 961 * NHEADS, att);
        tf_gemm<2><<<dim3(DIM / 128, TOKENS / 128), 256, GEMM_SMEM>>>(
            att, projwt + (size_t)i * DIM * DIM, proj_b + (size_t)i * DIM, h,
            TOKENS, DIM, DIM);
        ln_kernel<<<TOKENS / 8, 256>>>(h, ln2_g + i * DIM, ln2_b + i * DIM, ln);
        tf_gemm<1><<<dim3(HID / 128, TOKENS / 128), 256, GEMM_SMEM>>>(
            ln, fc1wt + (size_t)i * HID * DIM, fc1_b + (size_t)i * HID, hid,
            TOKENS, HID, DIM);
        tf_gemm<2><<<dim3(DIM / 128, TOKENS / 128), 256, GEMM_SMEM>>>(
            hid, fc2wt + (size_t)i * DIM * HID, fc2_b + (size_t)i * DIM, h,
            TOKENS, DIM, HID);
    }

    unpartition_kernel<<<TOKENS * 96 / 256, 256>>>(h, (float*)d_out);
}

// round 6
// speedup vs baseline: 2.4081x; 1.1859x over previous
#include <cuda_runtime.h>
#include <cuda_fp16.h>
#include <math.h>
#include <stdint.h>

// ---------------- problem constants ----------------
#define TOKENS   32768
#define DIM      384
#define NHEADS   8
#define HD       48
#define HID      1536
#define NWIN     128
#define WTOK     256
#define SCALE    0.14433756729740643f
#define LN_EPS   1e-5f

// ---------------- scratch ----------------
__device__ float  g_h   [(size_t)TOKENS * DIM];      // residual (fp32, natural)
__device__ __half g_ln  [(size_t)TOKENS * DIM];      // LN out (fp16, k-permuted)
__device__ float  g_qkv [(size_t)TOKENS * 3 * DIM];  // qkv (fp32, natural)
__device__ __half g_att [(size_t)TOKENS * DIM];      // attn out (fp16, k-permuted)
__device__ __half g_hid [(size_t)TOKENS * HID];      // mlp hidden (fp16, k-permuted)
// weights: [N][K] fp16, k-permuted
__device__ __half g_qkvwt[(size_t)2 * 3 * DIM * DIM];
__device__ __half g_projwt[(size_t)2 * DIM * DIM];
__device__ __half g_fc1wt[(size_t)2 * HID * DIM];
__device__ __half g_fc2wt[(size_t)2 * DIM * HID];

// in-32-block k permutation: thread tig reads halfs [8*tig, 8*tig+8) as one LDS.128
// covering k = {2tig,2tig+1, 2tig+8,2tig+9, 2tig+16,2tig+17, 2tig+24,2tig+25}
__host__ __device__ __forceinline__ int pos8(int c) {   // c in [0,32)
    int q = c >> 3, r = c & 7;
    return ((r >> 1) << 3) + (q << 1) + (r & 1);
}
__device__ __forceinline__ int permc(int c) {            // full channel index
    return (c & ~31) + pos8(c & 31);
}

// ---------------- helpers ----------------
__device__ __forceinline__ uint32_t smem_u32(const void* p) {
    uint32_t a;
    asm("{ .reg .u64 t; cvta.to.shared.u64 t, %1; cvt.u32.u64 %0, t; }" : "=r"(a) : "l"(p));
    return a;
}
__device__ __forceinline__ void cp16(uint32_t dst, const void* src) {
    asm volatile("cp.async.cg.shared.global [%0], [%1], 16;" :: "r"(dst), "l"(src));
}
__device__ __forceinline__ void cp_commit() {
    asm volatile("cp.async.commit_group;" ::: "memory");
}
template<int N>
__device__ __forceinline__ void cp_wait() {
    asm volatile("cp.async.wait_group %0;" :: "n"(N) : "memory");
}
__device__ __forceinline__ void mma_f16(float* d, uint32_t a0, uint32_t a1, uint32_t a2,
                                        uint32_t a3, uint32_t b0, uint32_t b1) {
    asm volatile(
        "mma.sync.aligned.m16n8k16.row.col.f32.f16.f16.f32 "
        "{%0,%1,%2,%3}, {%4,%5,%6,%7}, {%8,%9}, {%0,%1,%2,%3};"
        : "+f"(d[0]), "+f"(d[1]), "+f"(d[2]), "+f"(d[3])
        : "r"(a0), "r"(a1), "r"(a2), "r"(a3), "r"(b0), "r"(b1));
}
__device__ __forceinline__ float gelu_f(float x) {
    return 0.5f * x * (1.0f + erff(x * 0.70710678118654752f));
}

// ---------------- window partition / unpartition ----------------
__global__ void partition_kernel(const float* __restrict__ x, float* __restrict__ h) {
    int idx = blockIdx.x * 256 + threadIdx.x;
    int c4  = idx % 96;
    int tok = idx / 96;
    int n   = tok & 255;
    int win = tok >> 8;
    int wx = win & 7, wy = (win >> 3) & 7, b = win >> 6;
    int yi = n >> 4, xi = n & 15;
    size_t src = ((((size_t)b * 128 + wy * 16 + yi) * 128) + wx * 16 + xi) * 96 + c4;
    ((float4*)h)[idx] = ((const float4*)x)[src];
}

__global__ void unpartition_kernel(const float* __restrict__ h, float* __restrict__ out) {
    int idx = blockIdx.x * 256 + threadIdx.x;
    int c4  = idx % 96;
    int tok = idx / 96;
    int n   = tok & 255;
    int win = tok >> 8;
    int wx = win & 7, wy = (win >> 3) & 7, b = win >> 6;
    int yi = n >> 4, xi = n & 15;
    size_t dst = ((((size_t)b * 128 + wy * 16 + yi) * 128) + wx * 16 + xi) * 96 + c4;
    ((float4*)out)[dst] = ((const float4*)h)[idx];
}

// ---------------- layernorm -> fp16 permuted ----------------
__global__ void ln_kernel(const float* __restrict__ in, const float* __restrict__ g,
                          const float* __restrict__ b, __half* __restrict__ out) {
    int token = blockIdx.x * 8 + (threadIdx.x >> 5);
    int lane  = threadIdx.x & 31;
    const float* row = in + (size_t)token * DIM;
    float v[12];
    float s = 0.f;
    #pragma unroll
    for (int i = 0; i < 12; i++) { v[i] = row[lane + i * 32]; s += v[i]; }
    #pragma unroll
    for (int o = 16; o; o >>= 1) s += __shfl_xor_sync(0xffffffffu, s, o);
    float mu = s * (1.f / DIM);
    float vsum = 0.f;
    #pragma unroll
    for (int i = 0; i < 12; i++) { float d = v[i] - mu; vsum += d * d; }
    #pragma unroll
    for (int o = 16; o; o >>= 1) vsum += __shfl_xor_sync(0xffffffffu, vsum, o);
    float rstd = rsqrtf(vsum * (1.f / DIM) + LN_EPS);
    __half* orow = out + (size_t)token * DIM;
    int pp = pos8(lane);
    #pragma unroll
    for (int i = 0; i < 12; i++) {
        int c = lane + i * 32;
        orow[i * 32 + pp] = __float2half((v[i] - mu) * rstd * g[c] + b[c]);
    }
}

// ---------------- weight transpose: fp32 [K][N] -> fp16 [N][perm(K)] ----------------
__global__ void transpose_kernel(const float* __restrict__ in, __half* __restrict__ out,
                                 int K, int N) {
    __shared__ float t[32][33];
    int n0 = blockIdx.x * 32, k0 = blockIdx.y * 32;
    int x = threadIdx.x, y = threadIdx.y;
    #pragma unroll
    for (int i = 0; i < 32; i += 8)
        t[y + i][x] = in[(size_t)(k0 + y + i) * N + n0 + x];
    __syncthreads();
    int pp = pos8(x);
    #pragma unroll
    for (int i = 0; i < 32; i += 8)
        out[(size_t)(n0 + y + i) * K + k0 + pp] = __float2half(t[x][y + i]);
}

// ---------------- fp16 mma GEMM: 128x128 tile, BK=32, 4-stage cp.async ----------------
// A [M][K] fp16 permuted; B [N][K] fp16 permuted.
// MODE 0: out = A@B (fp32, natural)
// MODE 1: out = gelu(A@B + bias) (fp16, permuted)
// MODE 2: out(fp32) += A@B + bias
#define STG_BYTES 16384              // A 8KB + B 8KB
#define NSTAGE    4
#define GEMM_SMEM (NSTAGE * STG_BYTES)

template<int MODE>
__global__ void __launch_bounds__(256)
hgemm(const __half* __restrict__ A, const __half* __restrict__ Bt,
      const float* __restrict__ bias, void* __restrict__ Cv,
      int M, int N, int K) {
    extern __shared__ char smem[];
    uint32_t sbase = smem_u32(smem);

    int tid = threadIdx.x;
    int lane = tid & 31, wid = tid >> 5;
    int gid = lane >> 2, tig = lane & 3;
    int wm = wid & 3, wn = wid >> 2;               // 4x2 warp grid, warp tile 32x64
    int bm = blockIdx.y * 128, bn = blockIdx.x * 128;

    // cp.async mapping: 512 x 16B per stage (A 256, B 256); thread does 2+2
    int r0 = tid >> 1;            // rows 0..127 (two threads per row)
    int c0 = (tid & 1) * 2;       // chunk pair

    int T = K / 32;
    auto issue = [&](int t, int slot) {
        uint32_t ab = sbase + slot * STG_BYTES;
        uint32_t bb = ab + 8192;
        const __half* ag = A  + (size_t)(bm + r0) * K + t * 32 + c0 * 8;
        const __half* bg = Bt + (size_t)(bn + r0) * K + t * 32 + c0 * 8;
        cp16(ab + r0 * 64 + c0 * 16, ag);
        cp16(ab + r0 * 64 + c0 * 16 + 16, ag + 8);
        cp16(bb + r0 * 64 + c0 * 16, bg);
        cp16(bb + r0 * 64 + c0 * 16 + 16, bg + 8);
        cp_commit();
    };

    // prologue: 4 stages in flight (T >= 4 always here: min K = 384 -> T = 12)
    issue(0, 0); issue(1, 1); issue(2, 2); issue(3, 3);

    float acc[2][8][4];
    #pragma unroll
    for (int mt = 0; mt < 2; mt++)
        #pragma unroll
        for (int nt = 0; nt < 8; nt++)
            #pragma unroll
            for (int r = 0; r < 4; r++) acc[mt][nt][r] = 0.f;

    for (int t = 0; t < T; t++) {
        // invariant: pending groups must be <= issued - (t+1); issued = min(4+t, T)
        int rem = T - 1 - t;
        if (rem >= 3)      cp_wait<3>();
        else if (rem == 2) cp_wait<2>();
        else if (rem == 1) cp_wait<1>();
        else               cp_wait<0>();
        __syncthreads();

        int slot = t & 3;
        const char* as = smem + slot * STG_BYTES;
        const char* bs = as + 8192;

        uint4 aa[2][2];
        #pragma unroll
        for (int mt = 0; mt < 2; mt++) {
            int r = wm * 32 + mt * 16 + gid;
            aa[mt][0] = *(const uint4*)(as + r * 64 + tig * 16);
            aa[mt][1] = *(const uint4*)(as + (r + 8) * 64 + tig * 16);
        }
        #pragma unroll
        for (int nt = 0; nt < 8; nt++) {
            int n = wn * 64 + nt * 8 + gid;
            uint4 bb = *(const uint4*)(bs + n * 64 + tig * 16);
            #pragma unroll
            for (int mt = 0; mt < 2; mt++) {
                mma_f16(acc[mt][nt], aa[mt][0].x, aa[mt][1].x, aa[mt][0].y, aa[mt][1].y,
                        bb.x, bb.y);
                mma_f16(acc[mt][nt], aa[mt][0].z, aa[mt][1].z, aa[mt][0].w, aa[mt][1].w,
                        bb.z, bb.w);
            }
        }
        __syncthreads();                 // all reads of this slot done before refill
        if (t + 4 < T) issue(t + 4, (t + 4) & 3);
    }

    // epilogue
    #pragma unroll
    for (int nt = 0; nt < 8; nt++) {
        int col = bn + wn * 64 + nt * 8 + 2 * tig;
        float2 bv = make_float2(0.f, 0.f);
        if (MODE != 0) { bv.x = bias[col]; bv.y = bias[col + 1]; }
        int pc0 = permc(col), pc1 = permc(col + 1);
        #pragma unroll
        for (int mt = 0; mt < 2; mt++) {
            int rr = bm + wm * 32 + mt * 16 + gid;
            #pragma unroll
            for (int h = 0; h < 2; h++) {
                int row = rr + h * 8;
                float v0 = acc[mt][nt][h * 2 + 0];
                float v1 = acc[mt][nt][h * 2 + 1];
                if (MODE == 0) {
                    float* cp = (float*)Cv + (size_t)row * N + col;
                    *(float2*)cp = make_float2(v0, v1);
                } else if (MODE == 1) {
                    __half* cp = (__half*)Cv + (size_t)row * N;
                    cp[pc0] = __float2half(gelu_f(v0 + bv.x));
                    cp[pc1] = __float2half(gelu_f(v1 + bv.y));
                } else {
                    float* cp = (float*)Cv + (size_t)row * N + col;
                    float2 c0 = *(const float2*)cp;
                    c0.x += v0 + bv.x;
                    c0.y += v1 + bv.y;
                    *(float2*)cp = c0;
                }
            }
        }
    }
}

// ---------------- windowed attention (fp32 math, fp16-permuted output) ----------------
__global__ void __launch_bounds__(256)
attn_kernel(const float* __restrict__ qkv, const float* __restrict__ rpb,
            __half* __restrict__ out) {
    extern __shared__ float smemf[];
    float* ks = smemf;
    float* vs = smemf + WTOK * HD;

    int head = blockIdx.x;
    int win  = blockIdx.y;
    int n    = threadIdx.x;
    size_t base = (size_t)win * WTOK;

    const float* kbase = qkv + base * (3 * DIM) + DIM     + head * HD;
    const float* vbase = qkv + base * (3 * DIM) + 2 * DIM + head * HD;
    for (int idx = n; idx < WTOK * 12; idx += 256) {
        int m  = idx / 12;
        int d4 = (idx % 12) * 4;
        *(float4*)&ks[m * HD + d4] = *(const float4*)(kbase + (size_t)m * (3 * DIM) + d4);
        *(float4*)&vs[m * HD + d4] = *(const float4*)(vbase + (size_t)m * (3 * DIM) + d4);
    }
    __syncthreads();

    float q[HD];
    const float* qrow = qkv + (base + n) * (3 * DIM) + head * HD;
    #pragma unroll
    for (int d4 = 0; d4 < HD; d4 += 4) {
        float4 t = *(const float4*)(qrow + d4);
        q[d4 + 0] = t.x * SCALE; q[d4 + 1] = t.y * SCALE;
        q[d4 + 2] = t.z * SCALE; q[d4 + 3] = t.w * SCALE;
    }

    int yi = n >> 4, xi = n & 15;
    float mmax = -1e30f, l = 0.f;
    float o[HD];
    #pragma unroll
    for (int d = 0; d < HD; d++) o[d] = 0.f;

    for (int m0 = 0; m0 < WTOK; m0 += 8) {
        float s[8];
        #pragma unroll
        for (int j = 0; j < 8; j++) {
            const float* kr = &ks[(m0 + j) * HD];
            float a = 0.f;
            #pragma unroll
            for (int d = 0; d < HD; d++) a += q[d] * kr[d];
            int mm = m0 + j;
            int yj = mm >> 4, xj = mm & 15;
            int ridx = (yi - yj + 15) * 31 + (xi - xj + 15);
            s[j] = a + __ldg(rpb + ridx * NHEADS + head);
        }
        float cm = s[0];
        #pragma unroll
        for (int j = 1; j < 8; j++) cm = fmaxf(cm, s[j]);
        float nm = fmaxf(mmax, cm);
        float f = __expf(mmax - nm);
        float p[8], ps = 0.f;
        #pragma unroll
        for (int j = 0; j < 8; j++) { p[j] = __expf(s[j] - nm); ps += p[j]; }
        l = l * f + ps;
        #pragma unroll
        for (int d = 0; d < HD; d++) {
            float a = o[d] * f;
            #pragma unroll
            for (int j = 0; j < 8; j++) a += p[j] * vs[(m0 + j) * HD + d];
            o[d] = a;
        }
        mmax = nm;
    }

    float inv = 1.f / l;
    __half* orow = out + (base + n) * DIM;
    #pragma unroll
    for (int d = 0; d < HD; d++) {
        int c = head * HD + d;
        orow[(c & ~31) + pos8(c & 31)] = __float2half(o[d] * inv);
    }
}

// ---------------- host launcher ----------------
extern "C" void kernel_launch(void* const* d_in, const int* in_sizes, int n_in,
                              void* d_out, int out_size) {
    const float* x      = (const float*)d_in[0];
    const float* qkv_w  = (const float*)d_in[1];
    const float* proj_w = (const float*)d_in[2];
    const float* proj_b = (const float*)d_in[3];
    const float* rpb    = (const float*)d_in[4];
    const float* ln1_g  = (const float*)d_in[5];
    const float* ln1_b  = (const float*)d_in[6];
    const float* ln2_g  = (const float*)d_in[7];
    const float* ln2_b  = (const float*)d_in[8];
    const float* fc1_w  = (const float*)d_in[9];
    const float* fc1_b  = (const float*)d_in[10];
    const float* fc2_w  = (const float*)d_in[11];
    const float* fc2_b  = (const float*)d_in[12];

    float *h, *qkv;
    __half *ln, *att, *hid, *qkvwt, *projwt, *fc1wt, *fc2wt;
    cudaGetSymbolAddress((void**)&h,      g_h);
    cudaGetSymbolAddress((void**)&ln,     g_ln);
    cudaGetSymbolAddress((void**)&qkv,    g_qkv);
    cudaGetSymbolAddress((void**)&att,    g_att);
    cudaGetSymbolAddress((void**)&hid,    g_hid);
    cudaGetSymbolAddress((void**)&qkvwt,  g_qkvwt);
    cudaGetSymbolAddress((void**)&projwt, g_projwt);
    cudaGetSymbolAddress((void**)&fc1wt,  g_fc1wt);
    cudaGetSymbolAddress((void**)&fc2wt,  g_fc2wt);

    const int ATTN_SMEM = 2 * WTOK * HD * (int)sizeof(float); // 96 KB
    cudaFuncSetAttribute(attn_kernel, cudaFuncAttributeMaxDynamicSharedMemorySize, ATTN_SMEM);
    cudaFuncSetAttribute(hgemm<0>, cudaFuncAttributeMaxDynamicSharedMemorySize, GEMM_SMEM);
    cudaFuncSetAttribute(hgemm<1>, cudaFuncAttributeMaxDynamicSharedMemorySize, GEMM_SMEM);
    cudaFuncSetAttribute(hgemm<2>, cudaFuncAttributeMaxDynamicSharedMemorySize, GEMM_SMEM);

    dim3 tb(32, 8);
    for (int i = 0; i < 2; i++) {
        transpose_kernel<<<dim3(3 * DIM / 32, DIM / 32), tb>>>(
            qkv_w + (size_t)i * DIM * 3 * DIM, qkvwt + (size_t)i * 3 * DIM * DIM, DIM, 3 * DIM);
        transpose_kernel<<<dim3(DIM / 32, DIM / 32), tb>>>(
            proj_w + (size_t)i * DIM * DIM, projwt + (size_t)i * DIM * DIM, DIM, DIM);
        transpose_kernel<<<dim3(HID / 32, DIM / 32), tb>>>(
            fc1_w + (size_t)i * DIM * HID, fc1wt + (size_t)i * HID * DIM, DIM, HID);
        transpose_kernel<<<dim3(DIM / 32, HID / 32), tb>>>(
            fc2_w + (size_t)i * HID * DIM, fc2wt + (size_t)i * DIM * HID, HID, DIM);
    }

    partition_kernel<<<TOKENS * 96 / 256, 256>>>(x, h);

    for (int i = 0; i < 2; i++) {
        ln_kernel<<<TOKENS / 8, 256>>>(h, ln1_g + i * DIM, ln1_b + i * DIM, ln);
        hgemm<0><<<dim3(3 * DIM / 128, TOKENS / 128), 256, GEMM_SMEM>>>(
            ln, qkvwt + (size_t)i * 3 * DIM * DIM, nullptr, qkv, TOKENS, 3 * DIM, DIM);
        attn_kernel<<<dim3(NHEADS, NWIN), 256, ATTN_SMEM>>>(
            qkv, rpb + (size_t)i * 961 * NHEADS, att);
        hgemm<2><<<dim3(DIM / 128, TOKENS / 128), 256, GEMM_SMEM>>>(
            att, projwt + (size_t)i * DIM * DIM, proj_b + (size_t)i * DIM, h,
            TOKENS, DIM, DIM);
        ln_kernel<<<TOKENS / 8, 256>>>(h, ln2_g + i * DIM, ln2_b + i * DIM, ln);
        hgemm<1><<<dim3(HID / 128, TOKENS / 128), 256, GEMM_SMEM>>>(
            ln, fc1wt + (size_t)i * HID * DIM, fc1_b + (size_t)i * HID, hid,
            TOKENS, HID, DIM);
        hgemm<2><<<dim3(DIM / 128, TOKENS / 128), 256, GEMM_SMEM>>>(
            hid, fc2wt + (size_t)i * DIM * HID, fc2_b + (size_t)i * DIM, h,
            TOKENS, DIM, HID);
    }

    unpartition_kernel<<<TOKENS * 96 / 256, 256>>>(h, (float*)d_out);
}

// round 7
// speedup vs baseline: 2.9177x; 1.2116x over previous
#include <cuda_runtime.h>
#include <cuda_fp16.h>
#include <math.h>
#include <stdint.h>

// ---------------- problem constants ----------------
#define TOKENS   32768
#define DIM      384
#define NHEADS   8
#define HD       48
#define HID      1536
#define NWIN     128
#define WTOK     256
#define SCALE    0.14433756729740643f
#define LN_EPS   1e-5f

// ---------------- scratch ----------------
__device__ float  g_h   [(size_t)TOKENS * DIM];      // residual (fp32, natural)
__device__ __half g_ln  [(size_t)TOKENS * DIM];      // LN out (fp16, k-permuted)
__device__ float  g_qkv [(size_t)TOKENS * 3 * DIM];  // qkv (fp32, natural)
__device__ __half g_att [(size_t)TOKENS * DIM];      // attn out (fp16, k-permuted)
__device__ __half g_hid [(size_t)TOKENS * HID];      // mlp hidden (fp16, k-permuted)
// weights: [N][K] fp16, k-permuted
__device__ __half g_qkvwt[(size_t)2 * 3 * DIM * DIM];
__device__ __half g_projwt[(size_t)2 * DIM * DIM];
__device__ __half g_fc1wt[(size_t)2 * HID * DIM];
__device__ __half g_fc2wt[(size_t)2 * DIM * HID];

// in-32-block k permutation (one LDS.128 per fragment set)
__host__ __device__ __forceinline__ int pos8(int c) {   // c in [0,32)
    int q = c >> 3, r = c & 7;
    return ((r >> 1) << 3) + (q << 1) + (r & 1);
}
__device__ __forceinline__ int permc(int c) {
    return (c & ~31) + pos8(c & 31);
}

// ---------------- helpers ----------------
__device__ __forceinline__ uint32_t smem_u32(const void* p) {
    uint32_t a;
    asm("{ .reg .u64 t; cvta.to.shared.u64 t, %1; cvt.u32.u64 %0, t; }" : "=r"(a) : "l"(p));
    return a;
}
__device__ __forceinline__ void cp16(uint32_t dst, const void* src) {
    asm volatile("cp.async.cg.shared.global [%0], [%1], 16;" :: "r"(dst), "l"(src));
}
__device__ __forceinline__ void cp_commit() {
    asm volatile("cp.async.commit_group;" ::: "memory");
}
template<int N>
__device__ __forceinline__ void cp_wait() {
    asm volatile("cp.async.wait_group %0;" :: "n"(N) : "memory");
}
__device__ __forceinline__ void mma_f16(float* d, uint32_t a0, uint32_t a1, uint32_t a2,
                                        uint32_t a3, uint32_t b0, uint32_t b1) {
    asm volatile(
        "mma.sync.aligned.m16n8k16.row.col.f32.f16.f16.f32 "
        "{%0,%1,%2,%3}, {%4,%5,%6,%7}, {%8,%9}, {%0,%1,%2,%3};"
        : "+f"(d[0]), "+f"(d[1]), "+f"(d[2]), "+f"(d[3])
        : "r"(a0), "r"(a1), "r"(a2), "r"(a3), "r"(b0), "r"(b1));
}
__device__ __forceinline__ float gelu_f(float x) {
    return 0.5f * x * (1.0f + erff(x * 0.70710678118654752f));
}

// ---------------- window partition / unpartition ----------------
__global__ void partition_kernel(const float* __restrict__ x, float* __restrict__ h) {
    int idx = blockIdx.x * 256 + threadIdx.x;
    int c4  = idx % 96;
    int tok = idx / 96;
    int n   = tok & 255;
    int win = tok >> 8;
    int wx = win & 7, wy = (win >> 3) & 7, b = win >> 6;
    int yi = n >> 4, xi = n & 15;
    size_t src = ((((size_t)b * 128 + wy * 16 + yi) * 128) + wx * 16 + xi) * 96 + c4;
    ((float4*)h)[idx] = ((const float4*)x)[src];
}

__global__ void unpartition_kernel(const float* __restrict__ h, float* __restrict__ out) {
    int idx = blockIdx.x * 256 + threadIdx.x;
    int c4  = idx % 96;
    int tok = idx / 96;
    int n   = tok & 255;
    int win = tok >> 8;
    int wx = win & 7, wy = (win >> 3) & 7, b = win >> 6;
    int yi = n >> 4, xi = n & 15;
    size_t dst = ((((size_t)b * 128 + wy * 16 + yi) * 128) + wx * 16 + xi) * 96 + c4;
    ((float4*)out)[dst] = ((const float4*)h)[idx];
}

// ---------------- layernorm -> fp16 permuted ----------------
__global__ void ln_kernel(const float* __restrict__ in, const float* __restrict__ g,
                          const float* __restrict__ b, __half* __restrict__ out) {
    int token = blockIdx.x * 8 + (threadIdx.x >> 5);
    int lane  = threadIdx.x & 31;
    const float* row = in + (size_t)token * DIM;
    float v[12];
    float s = 0.f;
    #pragma unroll
    for (int i = 0; i < 12; i++) { v[i] = row[lane + i * 32]; s += v[i]; }
    #pragma unroll
    for (int o = 16; o; o >>= 1) s += __shfl_xor_sync(0xffffffffu, s, o);
    float mu = s * (1.f / DIM);
    float vsum = 0.f;
    #pragma unroll
    for (int i = 0; i < 12; i++) { float d = v[i] - mu; vsum += d * d; }
    #pragma unroll
    for (int o = 16; o; o >>= 1) vsum += __shfl_xor_sync(0xffffffffu, vsum, o);
    float rstd = rsqrtf(vsum * (1.f / DIM) + LN_EPS);
    __half* orow = out + (size_t)token * DIM;
    int pp = pos8(lane);
    #pragma unroll
    for (int i = 0; i < 12; i++) {
        int c = lane + i * 32;
        orow[i * 32 + pp] = __float2half((v[i] - mu) * rstd * g[c] + b[c]);
    }
}

// ---------------- weight transpose: fp32 [K][N] -> fp16 [N][perm(K)] ----------------
__global__ void transpose_kernel(const float* __restrict__ in, __half* __restrict__ out,
                                 int K, int N) {
    __shared__ float t[32][33];
    int n0 = blockIdx.x * 32, k0 = blockIdx.y * 32;
    int x = threadIdx.x, y = threadIdx.y;
    #pragma unroll
    for (int i = 0; i < 32; i += 8)
        t[y + i][x] = in[(size_t)(k0 + y + i) * N + n0 + x];
    __syncthreads();
    int pp = pos8(x);
    #pragma unroll
    for (int i = 0; i < 32; i += 8)
        out[(size_t)(n0 + y + i) * K + k0 + pp] = __float2half(t[x][y + i]);
}

// ---------------- fp16 mma GEMM: 128x128 tile, BK=32, 4-slot/3-ahead cp.async ----------------
#define STG_BYTES 16384              // A 8KB + B 8KB
#define NSTAGE    4
#define GEMM_SMEM (NSTAGE * STG_BYTES)

template<int MODE>
__global__ void __launch_bounds__(256)
hgemm(const __half* __restrict__ A, const __half* __restrict__ Bt,
      const float* __restrict__ bias, void* __restrict__ Cv,
      int M, int N, int K) {
    extern __shared__ char smem[];
    uint32_t sbase = smem_u32(smem);

    int tid = threadIdx.x;
    int lane = tid & 31, wid = tid >> 5;
    int gid = lane >> 2, tig = lane & 3;
    int wm = wid & 3, wn = wid >> 2;               // 4x2 warp grid, warp tile 32x64
    int bm = blockIdx.y * 128, bn = blockIdx.x * 128;

    int r0 = tid >> 1;            // rows 0..127 (two threads per row)
    int c0 = (tid & 1) * 2;       // chunk pair

    int T = K / 32;
    auto issue = [&](int t, int slot) {
        uint32_t ab = sbase + slot * STG_BYTES;
        uint32_t bb = ab + 8192;
        const __half* ag = A  + (size_t)(bm + r0) * K + t * 32 + c0 * 8;
        const __half* bg = Bt + (size_t)(bn + r0) * K + t * 32 + c0 * 8;
        cp16(ab + r0 * 64 + c0 * 16, ag);
        cp16(ab + r0 * 64 + c0 * 16 + 16, ag + 8);
        cp16(bb + r0 * 64 + c0 * 16, bg);
        cp16(bb + r0 * 64 + c0 * 16 + 16, bg + 8);
        cp_commit();
    };

    // 3 stages in flight (T >= 12 here)
    issue(0, 0); issue(1, 1); issue(2, 2);

    float acc[2][8][4];
    #pragma unroll
    for (int mt = 0; mt < 2; mt++)
        #pragma unroll
        for (int nt = 0; nt < 8; nt++)
            #pragma unroll
            for (int r = 0; r < 4; r++) acc[mt][nt][r] = 0.f;

    for (int t = 0; t < T; t++) {
        // stage t must have landed: pending <= issued - (t+1)
        int rem = T - 1 - t;
        if (rem >= 2)      cp_wait<2>();
        else if (rem == 1) cp_wait<1>();
        else               cp_wait<0>();
        __syncthreads();
        // refill slot (t+3)&3 — its last readers finished at iter t-1, ordered by
        // the barrier above; consecutive issues hit distinct slots mod 4.
        if (t + 3 < T) issue(t + 3, (t + 3) & 3);

        int slot = t & 3;
        const char* as = smem + slot * STG_BYTES;
        const char* bs = as + 8192;

        uint4 aa[2][2];
        #pragma unroll
        for (int mt = 0; mt < 2; mt++) {
            int r = wm * 32 + mt * 16 + gid;
            aa[mt][0] = *(const uint4*)(as + r * 64 + tig * 16);
            aa[mt][1] = *(const uint4*)(as + (r + 8) * 64 + tig * 16);
        }
        #pragma unroll
        for (int nt = 0; nt < 8; nt++) {
            int n = wn * 64 + nt * 8 + gid;
            uint4 bb = *(const uint4*)(bs + n * 64 + tig * 16);
            #pragma unroll
            for (int mt = 0; mt < 2; mt++) {
                mma_f16(acc[mt][nt], aa[mt][0].x, aa[mt][1].x, aa[mt][0].y, aa[mt][1].y,
                        bb.x, bb.y);
                mma_f16(acc[mt][nt], aa[mt][0].z, aa[mt][1].z, aa[mt][0].w, aa[mt][1].w,
                        bb.z, bb.w);
            }
        }
    }

    // epilogue
    #pragma unroll
    for (int nt = 0; nt < 8; nt++) {
        int col = bn + wn * 64 + nt * 8 + 2 * tig;
        float2 bv = make_float2(0.f, 0.f);
        if (MODE != 0) { bv.x = bias[col]; bv.y = bias[col + 1]; }
        int pc0 = permc(col), pc1 = permc(col + 1);
        #pragma unroll
        for (int mt = 0; mt < 2; mt++) {
            int rr = bm + wm * 32 + mt * 16 + gid;
            #pragma unroll
            for (int h = 0; h < 2; h++) {
                int row = rr + h * 8;
                float v0 = acc[mt][nt][h * 2 + 0];
                float v1 = acc[mt][nt][h * 2 + 1];
                if (MODE == 0) {
                    float* cp = (float*)Cv + (size_t)row * N + col;
                    *(float2*)cp = make_float2(v0, v1);
                } else if (MODE == 1) {
                    __half* cp = (__half*)Cv + (size_t)row * N;
                    cp[pc0] = __float2half(gelu_f(v0 + bv.x));
                    cp[pc1] = __float2half(gelu_f(v1 + bv.y));
                } else {
                    float* cp = (float*)Cv + (size_t)row * N + col;
                    float2 c0 = *(const float2*)cp;
                    c0.x += v0 + bv.x;
                    c0.y += v1 + bv.y;
                    *(float2*)cp = c0;
                }
            }
        }
    }
}

// ---------------- windowed attention: 128 threads, 2 queries/thread ----------------
__global__ void __launch_bounds__(128)
attn_kernel(const float* __restrict__ qkv, const float* __restrict__ rpb,
            __half* __restrict__ out) {
    extern __shared__ float smemf[];
    float* ks = smemf;
    float* vs = smemf + WTOK * HD;

    int head = blockIdx.x;
    int win  = blockIdx.y;
    int tid  = threadIdx.x;
    size_t base = (size_t)win * WTOK;

    const float* kbase = qkv + base * (3 * DIM) + DIM     + head * HD;
    const float* vbase = qkv + base * (3 * DIM) + 2 * DIM + head * HD;
    for (int idx = tid; idx < WTOK * 12; idx += 128) {
        int m  = idx / 12;
        int d4 = (idx % 12) * 4;
        *(float4*)&ks[m * HD + d4] = *(const float4*)(kbase + (size_t)m * (3 * DIM) + d4);
        *(float4*)&vs[m * HD + d4] = *(const float4*)(vbase + (size_t)m * (3 * DIM) + d4);
    }
    __syncthreads();

    int n0 = tid, n1 = tid + 128;
    float q0[HD], q1[HD];
    {
        const float* qr0 = qkv + (base + n0) * (3 * DIM) + head * HD;
        const float* qr1 = qkv + (base + n1) * (3 * DIM) + head * HD;
        #pragma unroll
        for (int d4 = 0; d4 < HD; d4 += 4) {
            float4 t0 = *(const float4*)(qr0 + d4);
            float4 t1 = *(const float4*)(qr1 + d4);
            q0[d4 + 0] = t0.x * SCALE; q0[d4 + 1] = t0.y * SCALE;
            q0[d4 + 2] = t0.z * SCALE; q0[d4 + 3] = t0.w * SCALE;
            q1[d4 + 0] = t1.x * SCALE; q1[d4 + 1] = t1.y * SCALE;
            q1[d4 + 2] = t1.z * SCALE; q1[d4 + 3] = t1.w * SCALE;
        }
    }

    int yi0 = n0 >> 4, xi0 = n0 & 15;
    int yi1 = n1 >> 4, xi1 = n1 & 15;
    float mm0 = -1e30f, l0 = 0.f, mm1 = -1e30f, l1 = 0.f;
    float o0[HD], o1[HD];
    #pragma unroll
    for (int d = 0; d < HD; d++) { o0[d] = 0.f; o1[d] = 0.f; }

    for (int m0 = 0; m0 < WTOK; m0 += 8) {
        float s0[8], s1[8];
        #pragma unroll
        for (int j = 0; j < 8; j++) {
            const float* kr = &ks[(m0 + j) * HD];
            float a0 = 0.f, a1 = 0.f;
            #pragma unroll
            for (int d = 0; d < HD; d++) {
                float kv = kr[d];
                a0 += q0[d] * kv;
                a1 += q1[d] * kv;
            }
            int mm = m0 + j;
            int yj = mm >> 4, xj = mm & 15;
            s0[j] = a0 + __ldg(rpb + ((yi0 - yj + 15) * 31 + (xi0 - xj + 15)) * NHEADS + head);
            s1[j] = a1 + __ldg(rpb + ((yi1 - yj + 15) * 31 + (xi1 - xj + 15)) * NHEADS + head);
        }
        float cm0 = s0[0], cm1 = s1[0];
        #pragma unroll
        for (int j = 1; j < 8; j++) { cm0 = fmaxf(cm0, s0[j]); cm1 = fmaxf(cm1, s1[j]); }
        float nm0 = fmaxf(mm0, cm0), nm1 = fmaxf(mm1, cm1);
        float f0 = __expf(mm0 - nm0), f1 = __expf(mm1 - nm1);
        float p0[8], p1[8], ps0 = 0.f, ps1 = 0.f;
        #pragma unroll
        for (int j = 0; j < 8; j++) {
            p0[j] = __expf(s0[j] - nm0); ps0 += p0[j];
            p1[j] = __expf(s1[j] - nm1); ps1 += p1[j];
        }
        l0 = l0 * f0 + ps0;
        l1 = l1 * f1 + ps1;
        #pragma unroll
        for (int d = 0; d < HD; d++) {
            float a0 = o0[d] * f0, a1 = o1[d] * f1;
            #pragma unroll
            for (int j = 0; j < 8; j++) {
                float vv = vs[(m0 + j) * HD + d];
                a0 += p0[j] * vv;
                a1 += p1[j] * vv;
            }
            o0[d] = a0; o1[d] = a1;
        }
        mm0 = nm0; mm1 = nm1;
    }

    float inv0 = 1.f / l0, inv1 = 1.f / l1;
    __half* or0 = out + (base + n0) * DIM;
    __half* or1 = out + (base + n1) * DIM;
    #pragma unroll
    for (int d = 0; d < HD; d++) {
        int c = head * HD + d;
        int pc = (c & ~31) + pos8(c & 31);
        or0[pc] = __float2half(o0[d] * inv0);
        or1[pc] = __float2half(o1[d] * inv1);
    }
}

// ---------------- host launcher ----------------
extern "C" void kernel_launch(void* const* d_in, const int* in_sizes, int n_in,
                              void* d_out, int out_size) {
    const float* x      = (const float*)d_in[0];
    const float* qkv_w  = (const float*)d_in[1];
    const float* proj_w = (const float*)d_in[2];
    const float* proj_b = (const float*)d_in[3];
    const float* rpb    = (const float*)d_in[4];
    const float* ln1_g  = (const float*)d_in[5];
    const float* ln1_b  = (const float*)d_in[6];
    const float* ln2_g  = (const float*)d_in[7];
    const float* ln2_b  = (const float*)d_in[8];
    const float* fc1_w  = (const float*)d_in[9];
    const float* fc1_b  = (const float*)d_in[10];
    const float* fc2_w  = (const float*)d_in[11];
    const float* fc2_b  = (const float*)d_in[12];

    float *h, *qkv;
    __half *ln, *att, *hid, *qkvwt, *projwt, *fc1wt, *fc2wt;
    cudaGetSymbolAddress((void**)&h,      g_h);
    cudaGetSymbolAddress((void**)&ln,     g_ln);
    cudaGetSymbolAddress((void**)&qkv,    g_qkv);
    cudaGetSymbolAddress((void**)&att,    g_att);
    cudaGetSymbolAddress((void**)&hid,    g_hid);
    cudaGetSymbolAddress((void**)&qkvwt,  g_qkvwt);
    cudaGetSymbolAddress((void**)&projwt, g_projwt);
    cudaGetSymbolAddress((void**)&fc1wt,  g_fc1wt);
    cudaGetSymbolAddress((void**)&fc2wt,  g_fc2wt);

    const int ATTN_SMEM = 2 * WTOK * HD * (int)sizeof(float); // 96 KB
    cudaFuncSetAttribute(attn_kernel, cudaFuncAttributeMaxDynamicSharedMemorySize, ATTN_SMEM);
    cudaFuncSetAttribute(hgemm<0>, cudaFuncAttributeMaxDynamicSharedMemorySize, GEMM_SMEM);
    cudaFuncSetAttribute(hgemm<1>, cudaFuncAttributeMaxDynamicSharedMemorySize, GEMM_SMEM);
    cudaFuncSetAttribute(hgemm<2>, cudaFuncAttributeMaxDynamicSharedMemorySize, GEMM_SMEM);

    dim3 tb(32, 8);
    for (int i = 0; i < 2; i++) {
        transpose_kernel<<<dim3(3 * DIM / 32, DIM / 32), tb>>>(
            qkv_w + (size_t)i * DIM * 3 * DIM, qkvwt + (size_t)i * 3 * DIM * DIM, DIM, 3 * DIM);
        transpose_kernel<<<dim3(DIM / 32, DIM / 32), tb>>>(
            proj_w + (size_t)i * DIM * DIM, projwt + (size_t)i * DIM * DIM, DIM, DIM);
        transpose_kernel<<<dim3(HID / 32, DIM / 32), tb>>>(
            fc1_w + (size_t)i * DIM * HID, fc1wt + (size_t)i * HID * DIM, DIM, HID);
        transpose_kernel<<<dim3(DIM / 32, HID / 32), tb>>>(
            fc2_w + (size_t)i * HID * DIM, fc2wt + (size_t)i * DIM * HID, HID, DIM);
    }

    partition_kernel<<<TOKENS * 96 / 256, 256>>>(x, h);

    for (int i = 0; i < 2; i++) {
        ln_kernel<<<TOKENS / 8, 256>>>(h, ln1_g + i * DIM, ln1_b + i * DIM, ln);
        hgemm<0><<<dim3(3 * DIM / 128, TOKENS / 128), 256, GEMM_SMEM>>>(
            ln, qkvwt + (size_t)i * 3 * DIM * DIM, nullptr, qkv, TOKENS, 3 * DIM, DIM);
        attn_kernel<<<dim3(NHEADS, NWIN), 128, ATTN_SMEM>>>(
            qkv, rpb + (size_t)i * 961 * NHEADS, att);
        hgemm<2><<<dim3(DIM / 128, TOKENS / 128), 256, GEMM_SMEM>>>(
            att, projwt + (size_t)i * DIM * DIM, proj_b + (size_t)i * DIM, h,
            TOKENS, DIM, DIM);
        ln_kernel<<<TOKENS / 8, 256>>>(h, ln2_g + i * DIM, ln2_b + i * DIM, ln);
        hgemm<1><<<dim3(HID / 128, TOKENS / 128), 256, GEMM_SMEM>>>(
            ln, fc1wt + (size_t)i * HID * DIM, fc1_b + (size_t)i * HID, hid,
            TOKENS, HID, DIM);
        hgemm<2><<<dim3(DIM / 128, TOKENS / 128), 256, GEMM_SMEM>>>(
            hid, fc2wt + (size_t)i * DIM * HID, fc2_b + (size_t)i * DIM, h,
            TOKENS, DIM, HID);
    }

    unpartition_kernel<<<TOKENS * 96 / 256, 256>>>(h, (float*)d_out);
}

// round 8
// speedup vs baseline: 4.0851x; 1.4001x over previous
#include <cuda_runtime.h>
#include <cuda_fp16.h>
#include <math.h>
#include <stdint.h>

// ---------------- problem constants ----------------
#define TOKENS   32768
#define DIM      384
#define NHEADS   8
#define HD       48
#define HID      1536
#define NWIN     128
#define WTOK     256
#define SCALE    0.14433756729740643f
#define LN_EPS   1e-5f

// ---------------- scratch ----------------
__device__ float  g_h   [(size_t)TOKENS * DIM];      // residual (fp32, natural)
__device__ __half g_ln  [(size_t)TOKENS * DIM];      // LN out (fp16, k-permuted)
__device__ float  g_qkv [(size_t)TOKENS * 3 * DIM];  // qkv (fp32, natural)
__device__ __half g_att [(size_t)TOKENS * DIM];      // attn out (fp16, k-permuted)
__device__ __half g_hid [(size_t)TOKENS * HID];      // mlp hidden (fp16, k-permuted)
// weights: [N][K] fp16, k-permuted
__device__ __half g_qkvwt[(size_t)2 * 3 * DIM * DIM];
__device__ __half g_projwt[(size_t)2 * DIM * DIM];
__device__ __half g_fc1wt[(size_t)2 * HID * DIM];
__device__ __half g_fc2wt[(size_t)2 * DIM * HID];

// in-32-block k permutation (one LDS.128 per fragment set)
__host__ __device__ __forceinline__ int pos8(int c) {   // c in [0,32)
    int q = c >> 3, r = c & 7;
    return ((r >> 1) << 3) + (q << 1) + (r & 1);
}
__device__ __forceinline__ int permc(int c) {
    return (c & ~31) + pos8(c & 31);
}

// ---------------- helpers ----------------
__device__ __forceinline__ uint32_t smem_u32(const void* p) {
    uint32_t a;
    asm("{ .reg .u64 t; cvta.to.shared.u64 t, %1; cvt.u32.u64 %0, t; }" : "=r"(a) : "l"(p));
    return a;
}
__device__ __forceinline__ void cp16(uint32_t dst, const void* src) {
    asm volatile("cp.async.cg.shared.global [%0], [%1], 16;" :: "r"(dst), "l"(src));
}
__device__ __forceinline__ void cp_commit() {
    asm volatile("cp.async.commit_group;" ::: "memory");
}
template<int N>
__device__ __forceinline__ void cp_wait() {
    asm volatile("cp.async.wait_group %0;" :: "n"(N) : "memory");
}
__device__ __forceinline__ void mma_f16(float* d, uint32_t a0, uint32_t a1, uint32_t a2,
                                        uint32_t a3, uint32_t b0, uint32_t b1) {
    asm volatile(
        "mma.sync.aligned.m16n8k16.row.col.f32.f16.f16.f32 "
        "{%0,%1,%2,%3}, {%4,%5,%6,%7}, {%8,%9}, {%0,%1,%2,%3};"
        : "+f"(d[0]), "+f"(d[1]), "+f"(d[2]), "+f"(d[3])
        : "r"(a0), "r"(a1), "r"(a2), "r"(a3), "r"(b0), "r"(b1));
}
__device__ __forceinline__ uint32_t pack_h2(float a, float b) {
    __half2 h = __floats2half2_rn(a, b);
    return *reinterpret_cast<uint32_t*>(&h);
}
__device__ __forceinline__ float gelu_f(float x) {
    return 0.5f * x * (1.0f + erff(x * 0.70710678118654752f));
}

// ---------------- window partition / unpartition ----------------
__global__ void partition_kernel(const float* __restrict__ x, float* __restrict__ h) {
    int idx = blockIdx.x * 256 + threadIdx.x;
    int c4  = idx % 96;
    int tok = idx / 96;
    int n   = tok & 255;
    int win = tok >> 8;
    int wx = win & 7, wy = (win >> 3) & 7, b = win >> 6;
    int yi = n >> 4, xi = n & 15;
    size_t src = ((((size_t)b * 128 + wy * 16 + yi) * 128) + wx * 16 + xi) * 96 + c4;
    ((float4*)h)[idx] = ((const float4*)x)[src];
}

__global__ void unpartition_kernel(const float* __restrict__ h, float* __restrict__ out) {
    int idx = blockIdx.x * 256 + threadIdx.x;
    int c4  = idx % 96;
    int tok = idx / 96;
    int n   = tok & 255;
    int win = tok >> 8;
    int wx = win & 7, wy = (win >> 3) & 7, b = win >> 6;
    int yi = n >> 4, xi = n & 15;
    size_t dst = ((((size_t)b * 128 + wy * 16 + yi) * 128) + wx * 16 + xi) * 96 + c4;
    ((float4*)out)[dst] = ((const float4*)h)[idx];
}

// ---------------- layernorm -> fp16 permuted ----------------
__global__ void ln_kernel(const float* __restrict__ in, const float* __restrict__ g,
                          const float* __restrict__ b, __half* __restrict__ out) {
    int token = blockIdx.x * 8 + (threadIdx.x >> 5);
    int lane  = threadIdx.x & 31;
    const float* row = in + (size_t)token * DIM;
    float v[12];
    float s = 0.f;
    #pragma unroll
    for (int i = 0; i < 12; i++) { v[i] = row[lane + i * 32]; s += v[i]; }
    #pragma unroll
    for (int o = 16; o; o >>= 1) s += __shfl_xor_sync(0xffffffffu, s, o);
    float mu = s * (1.f / DIM);
    float vsum = 0.f;
    #pragma unroll
    for (int i = 0; i < 12; i++) { float d = v[i] - mu; vsum += d * d; }
    #pragma unroll
    for (int o = 16; o; o >>= 1) vsum += __shfl_xor_sync(0xffffffffu, vsum, o);
    float rstd = rsqrtf(vsum * (1.f / DIM) + LN_EPS);
    __half* orow = out + (size_t)token * DIM;
    int pp = pos8(lane);
    #pragma unroll
    for (int i = 0; i < 12; i++) {
        int c = lane + i * 32;
        orow[i * 32 + pp] = __float2half((v[i] - mu) * rstd * g[c] + b[c]);
    }
}

// ---------------- weight transpose: fp32 [K][N] -> fp16 [N][perm(K)] ----------------
__global__ void transpose_kernel(const float* __restrict__ in, __half* __restrict__ out,
                                 int K, int N) {
    __shared__ float t[32][33];
    int n0 = blockIdx.x * 32, k0 = blockIdx.y * 32;
    int x = threadIdx.x, y = threadIdx.y;
    #pragma unroll
    for (int i = 0; i < 32; i += 8)
        t[y + i][x] = in[(size_t)(k0 + y + i) * N + n0 + x];
    __syncthreads();
    int pp = pos8(x);
    #pragma unroll
    for (int i = 0; i < 32; i += 8)
        out[(size_t)(n0 + y + i) * K + k0 + pp] = __float2half(t[x][y + i]);
}

// ---------------- fp16 mma GEMM: 128x128 tile, BK=32, 4-slot/3-ahead cp.async ----------------
#define STG_BYTES 16384              // A 8KB + B 8KB
#define NSTAGE    4
#define GEMM_SMEM (NSTAGE * STG_BYTES)

template<int MODE>
__global__ void __launch_bounds__(256)
hgemm(const __half* __restrict__ A, const __half* __restrict__ Bt,
      const float* __restrict__ bias, void* __restrict__ Cv,
      int M, int N, int K) {
    extern __shared__ char smem[];
    uint32_t sbase = smem_u32(smem);

    int tid = threadIdx.x;
    int lane = tid & 31, wid = tid >> 5;
    int gid = lane >> 2, tig = lane & 3;
    int wm = wid & 3, wn = wid >> 2;               // 4x2 warp grid, warp tile 32x64
    int bm = blockIdx.y * 128, bn = blockIdx.x * 128;

    int r0 = tid >> 1;            // rows 0..127 (two threads per row)
    int c0 = (tid & 1) * 2;       // chunk pair

    int T = K / 32;
    auto issue = [&](int t, int slot) {
        uint32_t ab = sbase + slot * STG_BYTES;
        uint32_t bb = ab + 8192;
        const __half* ag = A  + (size_t)(bm + r0) * K + t * 32 + c0 * 8;
        const __half* bg = Bt + (size_t)(bn + r0) * K + t * 32 + c0 * 8;
        cp16(ab + r0 * 64 + c0 * 16, ag);
        cp16(ab + r0 * 64 + c0 * 16 + 16, ag + 8);
        cp16(bb + r0 * 64 + c0 * 16, bg);
        cp16(bb + r0 * 64 + c0 * 16 + 16, bg + 8);
        cp_commit();
    };

    issue(0, 0); issue(1, 1); issue(2, 2);

    float acc[2][8][4];
    #pragma unroll
    for (int mt = 0; mt < 2; mt++)
        #pragma unroll
        for (int nt = 0; nt < 8; nt++)
            #pragma unroll
            for (int r = 0; r < 4; r++) acc[mt][nt][r] = 0.f;

    for (int t = 0; t < T; t++) {
        int rem = T - 1 - t;
        if (rem >= 2)      cp_wait<2>();
        else if (rem == 1) cp_wait<1>();
        else               cp_wait<0>();
        __syncthreads();
        if (t + 3 < T) issue(t + 3, (t + 3) & 3);

        int slot = t & 3;
        const char* as = smem + slot * STG_BYTES;
        const char* bs = as + 8192;

        uint4 aa[2][2];
        #pragma unroll
        for (int mt = 0; mt < 2; mt++) {
            int r = wm * 32 + mt * 16 + gid;
            aa[mt][0] = *(const uint4*)(as + r * 64 + tig * 16);
            aa[mt][1] = *(const uint4*)(as + (r + 8) * 64 + tig * 16);
        }
        #pragma unroll
        for (int nt = 0; nt < 8; nt++) {
            int n = wn * 64 + nt * 8 + gid;
            uint4 bb = *(const uint4*)(bs + n * 64 + tig * 16);
            #pragma unroll
            for (int mt = 0; mt < 2; mt++) {
                mma_f16(acc[mt][nt], aa[mt][0].x, aa[mt][1].x, aa[mt][0].y, aa[mt][1].y,
                        bb.x, bb.y);
                mma_f16(acc[mt][nt], aa[mt][0].z, aa[mt][1].z, aa[mt][0].w, aa[mt][1].w,
                        bb.z, bb.w);
            }
        }
    }

    #pragma unroll
    for (int nt = 0; nt < 8; nt++) {
        int col = bn + wn * 64 + nt * 8 + 2 * tig;
        float2 bv = make_float2(0.f, 0.f);
        if (MODE != 0) { bv.x = bias[col]; bv.y = bias[col + 1]; }
        int pc0 = permc(col), pc1 = permc(col + 1);
        #pragma unroll
        for (int mt = 0; mt < 2; mt++) {
            int rr = bm + wm * 32 + mt * 16 + gid;
            #pragma unroll
            for (int h = 0; h < 2; h++) {
                int row = rr + h * 8;
                float v0 = acc[mt][nt][h * 2 + 0];
                float v1 = acc[mt][nt][h * 2 + 1];
                if (MODE == 0) {
                    float* cp = (float*)Cv + (size_t)row * N + col;
                    *(float2*)cp = make_float2(v0, v1);
                } else if (MODE == 1) {
                    __half* cp = (__half*)Cv + (size_t)row * N;
                    cp[pc0] = __float2half(gelu_f(v0 + bv.x));
                    cp[pc1] = __float2half(gelu_f(v1 + bv.y));
                } else {
                    float* cp = (float*)Cv + (size_t)row * N + col;
                    float2 c0 = *(const float2*)cp;
                    c0.x += v0 + bv.x;
                    c0.y += v1 + bv.y;
                    *(float2*)cp = c0;
                }
            }
        }
    }
}

// ---------------- tensor-core flash attention ----------------
// CTA = (head, window), 8 warps x 32 query rows. fp16 MMA, fp32 softmax.
// smem: qs[256][64] fp16 (k-permuted, d 48..63 zero), ks same, vsT[48][264] fp16
// (key-permuted), bias table bs[961] fp32.
#define VS_STR    264
#define AT_QS     0
#define AT_KS     32768
#define AT_VS     65536
#define AT_BS     (65536 + 48 * VS_STR * 2)          // 90880
#define ATTN_SMEM (AT_BS + 961 * 4)                  // 94724

__global__ void __launch_bounds__(256)
attn_kernel(const float* __restrict__ qkv, const float* __restrict__ rpb,
            __half* __restrict__ out) {
    extern __shared__ char smem[];
    __half* qs = (__half*)(smem + AT_QS);
    __half* ks = (__half*)(smem + AT_KS);
    __half* vsT = (__half*)(smem + AT_VS);
    float*  bs = (float*)(smem + AT_BS);

    int head = blockIdx.x;
    int win  = blockIdx.y;
    int tid  = threadIdx.x;
    int lane = tid & 31, wid = tid >> 5;
    int gid = lane >> 2, tig = lane & 3;
    size_t base = (size_t)win * WTOK;

    // ---- staging ----
    // zero pad slots (raw d 48..63 -> permuted block1 slots 4..7 of each 8-group)
    for (int i = tid; i < 256 * 8; i += 256) {
        int row = i >> 3, g = (i >> 1) & 3, buf = i & 1;
        __half* p = (buf ? ks : qs) + row * 64 + 32 + g * 8 + 4;
        *(uint2*)p = make_uint2(0u, 0u);
    }
    const float* qbase = qkv + base * (3 * DIM) + head * HD;
    const float* kbase = qbase + DIM;
    const float* vbase = qbase + 2 * DIM;
    for (int idx = tid; idx < 256 * 12; idx += 256) {
        int m = idx / 12, c4 = (idx % 12) * 4;
        float4 tq = *(const float4*)(qbase + (size_t)m * (3 * DIM) + c4);
        float4 tk = *(const float4*)(kbase + (size_t)m * (3 * DIM) + c4);
        float4 tv = *(const float4*)(vbase + (size_t)m * (3 * DIM) + c4);
        int blk = c4 & ~31;
        int b0 = blk + (((c4 & 7) >> 1) << 3) + (((c4 & 31) >> 3) << 1);
        *(__half2*)&qs[m * 64 + b0]     = __floats2half2_rn(tq.x, tq.y);
        *(__half2*)&qs[m * 64 + b0 + 8] = __floats2half2_rn(tq.z, tq.w);
        *(__half2*)&ks[m * 64 + b0]     = __floats2half2_rn(tk.x, tk.y);
        *(__half2*)&ks[m * 64 + b0 + 8] = __floats2half2_rn(tk.z, tk.w);
        int pk = (m & ~31) + pos8(m & 31);
        vsT[(c4 + 0) * VS_STR + pk] = __float2half(tv.x);
        vsT[(c4 + 1) * VS_STR + pk] = __float2half(tv.y);
        vsT[(c4 + 2) * VS_STR + pk] = __float2half(tv.z);
        vsT[(c4 + 3) * VS_STR + pk] = __float2half(tv.w);
    }
    for (int i = tid; i < 961; i += 256)
        bs[i] = __ldg(rpb + i * NHEADS + head);
    __syncthreads();

    // ---- per-warp flash over 4 key blocks of 64 ----
    int wm = wid;
    // row indices: ri = mt*2 + half -> row = wm*32 + mt*16 + gid + half*8
    int rt[4];
    #pragma unroll
    for (int ri = 0; ri < 4; ri++) {
        int row = wm * 32 + (ri >> 1) * 16 + gid + (ri & 1) * 8;
        rt[ri] = (row >> 4) * 31 + (row & 15) + 480;
    }
    float m_[4] = {-1e30f, -1e30f, -1e30f, -1e30f};
    float l_[4] = {0.f, 0.f, 0.f, 0.f};
    float oacc[2][6][4];
    #pragma unroll
    for (int mt = 0; mt < 2; mt++)
        #pragma unroll
        for (int vt = 0; vt < 6; vt++)
            #pragma unroll
            for (int e = 0; e < 4; e++) oacc[mt][vt][e] = 0.f;

    uint4 qf[2][2][2];   // [mt][ktile][rowhalf]
    #pragma unroll
    for (int mt = 0; mt < 2; mt++)
        #pragma unroll
        for (int kt = 0; kt < 2; kt++) {
            int r = wm * 32 + mt * 16 + gid;
            qf[mt][kt][0] = *(const uint4*)&qs[r * 64 + kt * 32 + tig * 8];
            qf[mt][kt][1] = *(const uint4*)&qs[(r + 8) * 64 + kt * 32 + tig * 8];
        }

    for (int kb = 0; kb < WTOK; kb += 64) {
        float sacc[2][8][4];
        #pragma unroll
        for (int mt = 0; mt < 2; mt++)
            #pragma unroll
            for (int nt = 0; nt < 8; nt++)
                #pragma unroll
                for (int e = 0; e < 4; e++) sacc[mt][nt][e] = 0.f;

        #pragma unroll
        for (int nt = 0; nt < 8; nt++) {
            int kr = kb + nt * 8 + gid;
            uint4 kf0 = *(const uint4*)&ks[kr * 64 + tig * 8];
            uint4 kf1 = *(const uint4*)&ks[kr * 64 + 32 + tig * 8];
            #pragma unroll
            for (int mt = 0; mt < 2; mt++) {
                mma_f16(sacc[mt][nt], qf[mt][0][0].x, qf[mt][0][1].x,
                        qf[mt][0][0].y, qf[mt][0][1].y, kf0.x, kf0.y);
                mma_f16(sacc[mt][nt], qf[mt][0][0].z, qf[mt][0][1].z,
                        qf[mt][0][0].w, qf[mt][0][1].w, kf0.z, kf0.w);
                mma_f16(sacc[mt][nt], qf[mt][1][0].x, qf[mt][1][1].x,
                        qf[mt][1][0].y, qf[mt][1][1].y, kf1.x, kf1.y);
                mma_f16(sacc[mt][nt], qf[mt][1][0].z, qf[mt][1][1].z,
                        qf[mt][1][0].w, qf[mt][1][1].w, kf1.z, kf1.w);
            }
        }

        // scale + bias + row max
        float rmax[4] = {-1e30f, -1e30f, -1e30f, -1e30f};
        #pragma unroll
        for (int mt = 0; mt < 2; mt++)
            #pragma unroll
            for (int nt = 0; nt < 8; nt++)
                #pragma unroll
                for (int e = 0; e < 4; e++) {
                    int key = kb + nt * 8 + 2 * tig + (e & 1);
                    int ct = (key >> 4) * 31 + (key & 15);
                    int ri = mt * 2 + (e >> 1);
                    float s = sacc[mt][nt][e] * SCALE + bs[rt[ri] - ct];
                    sacc[mt][nt][e] = s;
                    rmax[ri] = fmaxf(rmax[ri], s);
                }
        #pragma unroll
        for (int ri = 0; ri < 4; ri++) {
            rmax[ri] = fmaxf(rmax[ri], __shfl_xor_sync(0xffffffffu, rmax[ri], 1));
            rmax[ri] = fmaxf(rmax[ri], __shfl_xor_sync(0xffffffffu, rmax[ri], 2));
        }
        float f_[4];
        #pragma unroll
        for (int ri = 0; ri < 4; ri++) {
            float nm = fmaxf(m_[ri], rmax[ri]);
            f_[ri] = __expf(m_[ri] - nm);
            m_[ri] = nm;
        }
        float rsum[4] = {0.f, 0.f, 0.f, 0.f};
        #pragma unroll
        for (int mt = 0; mt < 2; mt++)
            #pragma unroll
            for (int nt = 0; nt < 8; nt++)
                #pragma unroll
                for (int e = 0; e < 4; e++) {
                    int ri = mt * 2 + (e >> 1);
                    float p = __expf(sacc[mt][nt][e] - m_[ri]);
                    sacc[mt][nt][e] = p;
                    rsum[ri] += p;
                }
        #pragma unroll
        for (int ri = 0; ri < 4; ri++) {
            rsum[ri] += __shfl_xor_sync(0xffffffffu, rsum[ri], 1);
            rsum[ri] += __shfl_xor_sync(0xffffffffu, rsum[ri], 2);
            l_[ri] = l_[ri] * f_[ri] + rsum[ri];
        }
        #pragma unroll
        for (int mt = 0; mt < 2; mt++)
            #pragma unroll
            for (int vt = 0; vt < 6; vt++)
                #pragma unroll
                for (int e = 0; e < 4; e++)
                    oacc[mt][vt][e] *= f_[mt * 2 + (e >> 1)];

        // pack P fragments: two adjacent n8 C tiles = one k16 A fragment
        uint32_t pa[2][4][4];
        #pragma unroll
        for (int mt = 0; mt < 2; mt++)
            #pragma unroll
            for (int kk = 0; kk < 4; kk++) {
                pa[mt][kk][0] = pack_h2(sacc[mt][2 * kk][0], sacc[mt][2 * kk][1]);
                pa[mt][kk][1] = pack_h2(sacc[mt][2 * kk][2], sacc[mt][2 * kk][3]);
                pa[mt][kk][2] = pack_h2(sacc[mt][2 * kk + 1][0], sacc[mt][2 * kk + 1][1]);
                pa[mt][kk][3] = pack_h2(sacc[mt][2 * kk + 1][2], sacc[mt][2 * kk + 1][3]);
            }
        // P @ V
        #pragma unroll
        for (int vt = 0; vt < 6; vt++) {
            int vrow = vt * 8 + gid;
            uint4 vf0 = *(const uint4*)&vsT[vrow * VS_STR + kb + tig * 8];
            uint4 vf1 = *(const uint4*)&vsT[vrow * VS_STR + kb + 32 + tig * 8];
            #pragma unroll
            for (int mt = 0; mt < 2; mt++) {
                mma_f16(oacc[mt][vt], pa[mt][0][0], pa[mt][0][1], pa[mt][0][2], pa[mt][0][3],
                        vf0.x, vf0.y);
                mma_f16(oacc[mt][vt], pa[mt][1][0], pa[mt][1][1], pa[mt][1][2], pa[mt][1][3],
                        vf0.z, vf0.w);
                mma_f16(oacc[mt][vt], pa[mt][2][0], pa[mt][2][1], pa[mt][2][2], pa[mt][2][3],
                        vf1.x, vf1.y);
                mma_f16(oacc[mt][vt], pa[mt][3][0], pa[mt][3][1], pa[mt][3][2], pa[mt][3][3],
                        vf1.z, vf1.w);
            }
        }
    }

    // epilogue: O / l -> fp16 permuted
    #pragma unroll
    for (int mt = 0; mt < 2; mt++)
        #pragma unroll
        for (int h = 0; h < 2; h++) {
            int row = wm * 32 + mt * 16 + gid + h * 8;
            float inv = 1.f / l_[mt * 2 + h];
            __half* orow = out + (base + row) * DIM;
            #pragma unroll
            for (int vt = 0; vt < 6; vt++) {
                int d = vt * 8 + 2 * tig;
                int c = head * HD + d;
                int pc = (c & ~31) + pos8(c & 31);
                *(__half2*)&orow[pc] = __floats2half2_rn(
                    oacc[mt][vt][h * 2 + 0] * inv, oacc[mt][vt][h * 2 + 1] * inv);
            }
        }
}

// ---------------- host launcher ----------------
extern "C" void kernel_launch(void* const* d_in, const int* in_sizes, int n_in,
                              void* d_out, int out_size) {
    const float* x      = (const float*)d_in[0];
    const float* qkv_w  = (const float*)d_in[1];
    const float* proj_w = (const float*)d_in[2];
    const float* proj_b = (const float*)d_in[3];
    const float* rpb    = (const float*)d_in[4];
    const float* ln1_g  = (const float*)d_in[5];
    const float* ln1_b  = (const float*)d_in[6];
    const float* ln2_g  = (const float*)d_in[7];
    const float* ln2_b  = (const float*)d_in[8];
    const float* fc1_w  = (const float*)d_in[9];
    const float* fc1_b  = (const float*)d_in[10];
    const float* fc2_w  = (const float*)d_in[11];
    const float* fc2_b  = (const float*)d_in[12];

    float *h, *qkv;
    __half *ln, *att, *hid, *qkvwt, *projwt, *fc1wt, *fc2wt;
    cudaGetSymbolAddress((void**)&h,      g_h);
    cudaGetSymbolAddress((void**)&ln,     g_ln);
    cudaGetSymbolAddress((void**)&qkv,    g_qkv);
    cudaGetSymbolAddress((void**)&att,    g_att);
    cudaGetSymbolAddress((void**)&hid,    g_hid);
    cudaGetSymbolAddress((void**)&qkvwt,  g_qkvwt);
    cudaGetSymbolAddress((void**)&projwt, g_projwt);
    cudaGetSymbolAddress((void**)&fc1wt,  g_fc1wt);
    cudaGetSymbolAddress((void**)&fc2wt,  g_fc2wt);

    cudaFuncSetAttribute(attn_kernel, cudaFuncAttributeMaxDynamicSharedMemorySize, ATTN_SMEM);
    cudaFuncSetAttribute(hgemm<0>, cudaFuncAttributeMaxDynamicSharedMemorySize, GEMM_SMEM);
    cudaFuncSetAttribute(hgemm<1>, cudaFuncAttributeMaxDynamicSharedMemorySize, GEMM_SMEM);
    cudaFuncSetAttribute(hgemm<2>, cudaFuncAttributeMaxDynamicSharedMemorySize, GEMM_SMEM);

    dim3 tb(32, 8);
    for (int i = 0; i < 2; i++) {
        transpose_kernel<<<dim3(3 * DIM / 32, DIM / 32), tb>>>(
            qkv_w + (size_t)i * DIM * 3 * DIM, qkvwt + (size_t)i * 3 * DIM * DIM, DIM, 3 * DIM);
        transpose_kernel<<<dim3(DIM / 32, DIM / 32), tb>>>(
            proj_w + (size_t)i * DIM * DIM, projwt + (size_t)i * DIM * DIM, DIM, DIM);
        transpose_kernel<<<dim3(HID / 32, DIM / 32), tb>>>(
            fc1_w + (size_t)i * DIM * HID, fc1wt + (size_t)i * HID * DIM, DIM, HID);
        transpose_kernel<<<dim3(DIM / 32, HID / 32), tb>>>(
            fc2_w + (size_t)i * HID * DIM, fc2wt + (size_t)i * DIM * HID, HID, DIM);
    }

    partition_kernel<<<TOKENS * 96 / 256, 256>>>(x, h);

    for (int i = 0; i < 2; i++) {
        ln_kernel<<<TOKENS / 8, 256>>>(h, ln1_g + i * DIM, ln1_b + i * DIM, ln);
        hgemm<0><<<dim3(3 * DIM / 128, TOKENS / 128), 256, GEMM_SMEM>>>(
            ln, qkvwt + (size_t)i * 3 * DIM * DIM, nullptr, qkv, TOKENS, 3 * DIM, DIM);
        attn_kernel<<<dim3(NHEADS, NWIN), 256, ATTN_SMEM>>>(
            qkv, rpb + (size_t)i * 961 * NHEADS, att);
        hgemm<2><<<dim3(DIM / 128, TOKENS / 128), 256, GEMM_SMEM>>>(
            att, projwt + (size_t)i * DIM * DIM, proj_b + (size_t)i * DIM, h,
            TOKENS, DIM, DIM);
        ln_kernel<<<TOKENS / 8, 256>>>(h, ln2_g + i * DIM, ln2_b + i * DIM, ln);
        hgemm<1><<<dim3(HID / 128, TOKENS / 128), 256, GEMM_SMEM>>>(
            ln, fc1wt + (size_t)i * HID * DIM, fc1_b + (size_t)i * HID, hid,
            TOKENS, HID, DIM);
        hgemm<2><<<dim3(DIM / 128, TOKENS / 128), 256, GEMM_SMEM>>>(
            hid, fc2wt + (size_t)i * DIM * HID, fc2_b + (size_t)i * DIM, h,
            TOKENS, DIM, HID);
    }

    unpartition_kernel<<<TOKENS * 96 / 256, 256>>>(h, (float*)d_out);
}